// round 11
// baseline (speedup 1.0000x reference)
#include <cuda_runtime.h>
#include <cuda_fp16.h>
#include <math.h>
#include <stdint.h>

// Problem constants
#define Bb 4
#define Tt 2048
#define Dd 2048
#define DH 1024
#define KK 16
#define NH 16
#define HD 128
#define BT (Bb*Tt)          // 8192 rows
#define KPAD 1088
#define NSPLIT 8
#define HK 256              // NH*KK
#define SKS 4               // split-K for scores GEMM

// ---------------- scratch (device globals; no allocation) ----------------
__device__ float  g_mu[BT];
__device__ float  g_iv[BT];
__device__ __half g_S0h[(size_t)BT * Dd];       // LN_gca output (fp16)
__device__ __half g_S1h[(size_t)BT * Dd];       // sheaf pre (fp16)
__device__ __half g_Wh[(size_t)Dd * Dd];        // corr_W (fp16)
__device__ float  g_repr[64 * Dd];
__device__ float  g_Kh[64 * Dd];
__device__ float  g_Vv[64 * Dd];
__device__ float  g_packin[64 * KPAD];
__device__ float  g_Wpad[Dd * KPAD];
__device__ float  g_part[NSPLIT * 64 * Dd];
__device__ __half g_KWh[(size_t)Bb * HK * Dd];  // [b][hk][i]
__device__ __half g_VWTh[(size_t)Bb * Dd * HK]; // [b][o][hk]
__device__ float  g_scorep[(size_t)SKS * BT * HK];
__device__ __half g_Ph[(size_t)BT * HK];
__device__ float  g_shc[4 * DH];
__device__ float  g_shs[4 * DH];
__device__ float  g_gc[Bb * DH];
__device__ float  g_gs[Bb * DH];

// ---------------- helpers ----------------
__device__ __forceinline__ uint32_t smem_u32(const void* p) {
    uint32_t a;
    asm("{ .reg .u64 t; cvta.to.shared.u64 t, %1; cvt.u32.u64 %0, t; }" : "=r"(a) : "l"(p));
    return a;
}
__device__ __forceinline__ void cp16(uint32_t dst, const void* src) {
    asm volatile("cp.async.cg.shared.global [%0], [%1], 16;" :: "r"(dst), "l"(src));
}
__device__ __forceinline__ void ldsm_x4(uint32_t& r0, uint32_t& r1, uint32_t& r2, uint32_t& r3,
                                        uint32_t addr) {
    asm volatile("ldmatrix.sync.aligned.m8n8.x4.b16 {%0,%1,%2,%3}, [%4];"
                 : "=r"(r0), "=r"(r1), "=r"(r2), "=r"(r3) : "r"(addr));
}
__device__ __forceinline__ void mma_f16_16n8k16(float& c0, float& c1, float& c2, float& c3,
                                                uint32_t a0, uint32_t a1, uint32_t a2, uint32_t a3,
                                                uint32_t b0, uint32_t b1) {
    asm volatile(
        "mma.sync.aligned.m16n8k16.row.col.f32.f16.f16.f32 "
        "{%0,%1,%2,%3}, {%4,%5,%6,%7}, {%8,%9}, {%0,%1,%2,%3};"
        : "+f"(c0), "+f"(c1), "+f"(c2), "+f"(c3)
        : "r"(a0), "r"(a1), "r"(a2), "r"(a3), "r"(b0), "r"(b1));
}

// ============== fp16 warp-MMA NT GEMM: C(+add1 fp32)(+add2 fp16) = A @ W^T ==============
// NT = number of 64-half K-chunks (compile time). Kchunk = NT*64 halfs.
// A: [M,Kstride] fp16, W: [N,Kstride] fp16 (batched by bm>>11 via wbstride).
// blockIdx.z selects K-chunk slab (kofs = z*NT*64) and C slab (z*czstride).
// 128x128 tile, 8 warps 2x4 (warp 64x32), 3-stage cp.async, swizzled ldmatrix.
#define KC 64
#define HALF_STAGE 16384
#define STAGE_BYTES 32768
#define NSTAGE 3
#define GEMM_MMA_SMEM (NSTAGE * STAGE_BYTES)   // 98304

template<int NT>
__global__ void __launch_bounds__(256, 2) gemm_mma(const __half* __restrict__ A,
                                                   const __half* __restrict__ W,
                                                   float* __restrict__ C,
                                                   const float* __restrict__ add1,
                                                   const __half* __restrict__ add2h,
                                                   int N, int Kstride,
                                                   size_t wbstride, size_t czstride)
{
    extern __shared__ char dyn[];
    const int tid = threadIdx.x;
    const int bm = blockIdx.y * 128;
    const int bn = blockIdx.x * 128;
    const int kofs = blockIdx.z * (NT * KC);

    const int lane = tid & 31, wid = tid >> 5;
    const int wm = wid & 1, wn = wid >> 1;
    const int gid = lane >> 2, tig = lane & 3;
    const int am0 = wm * 64;
    const int bn0 = wn * 32;

    const uint32_t tile0 = smem_u32(dyn);
    const __half* Abase = A + (size_t)bm * Kstride + kofs;
    const __half* Wbase = W + (size_t)(bm >> 11) * wbstride + (size_t)bn * Kstride + kofs;
    C += (size_t)blockIdx.z * czstride;

    // hoisted per-thread cp.async addressing (stage-invariant parts)
    uint32_t dstA[4];
    const __half* srcA[4];
    const __half* srcB[4];
    {
#pragma unroll
        for (int i = 0; i < 4; i++) {
            int c = i * 256 + tid;               // 0..1023
            int row = c >> 3, ch = c & 7;
            uint32_t dof = (uint32_t)(row * 128 + ((ch ^ (row & 7)) << 4));
            dstA[i] = tile0 + dof;
            srcA[i] = Abase + (size_t)row * Kstride + ch * 8;
            srcB[i] = Wbase + (size_t)row * Kstride + ch * 8;
        }
    }

    const int lrow = lane & 7, lmat = lane >> 3;
    uint32_t aoff[4]; int arm[4];
#pragma unroll
    for (int mf = 0; mf < 4; mf++) {
        int r = am0 + mf * 16 + ((lmat & 1) << 3) + lrow;
        aoff[mf] = (uint32_t)(r * 128);
        arm[mf] = r & 7;
    }
    const int achunk_add = lmat >> 1;
    uint32_t boff[2]; int brm[2];
#pragma unroll
    for (int p = 0; p < 2; p++) {
        int r = bn0 + ((p * 2 + (lmat >> 1)) << 3) + lrow;
        boff[p] = (uint32_t)(r * 128);
        brm[p] = r & 7;
    }
    const int bchunk_add = lmat & 1;

    float acc[4][4][4];
#pragma unroll
    for (int i = 0; i < 4; i++)
#pragma unroll
        for (int j = 0; j < 4; j++)
#pragma unroll
            for (int r = 0; r < 4; r++) acc[i][j][r] = 0.f;

    auto load_stage = [&](int kt) {
        uint32_t sb = (uint32_t)((kt % NSTAGE) * STAGE_BYTES);
        int ko = kt * KC;
#pragma unroll
        for (int i = 0; i < 4; i++) {
            cp16(dstA[i] + sb,              srcA[i] + ko);
            cp16(dstA[i] + HALF_STAGE + sb, srcB[i] + ko);
        }
        asm volatile("cp.async.commit_group;" ::: "memory");
    };

    load_stage(0);
    if (NT > 1) load_stage(1);

    for (int kt = 0; kt < NT; kt++) {
        if (kt + 1 < NT) asm volatile("cp.async.wait_group 1;" ::: "memory");
        else             asm volatile("cp.async.wait_group 0;" ::: "memory");
        __syncthreads();
        if (kt + 2 < NT) load_stage(kt + 2);

        uint32_t As_u = tile0 + (kt % NSTAGE) * STAGE_BYTES;
        uint32_t Bs_u = As_u + HALF_STAGE;
#pragma unroll
        for (int ks = 0; ks < 4; ks++) {        // 4 x k16 per 64-half chunk
            uint32_t a[4][4], b[4][2];
#pragma unroll
            for (int mf = 0; mf < 4; mf++) {
                uint32_t addr = As_u + aoff[mf] +
                                (uint32_t)(((2 * ks + achunk_add) ^ arm[mf]) << 4);
                ldsm_x4(a[mf][0], a[mf][1], a[mf][2], a[mf][3], addr);
            }
#pragma unroll
            for (int p = 0; p < 2; p++) {
                uint32_t addr = Bs_u + boff[p] +
                                (uint32_t)(((2 * ks + bchunk_add) ^ brm[p]) << 4);
                ldsm_x4(b[2 * p][0], b[2 * p][1], b[2 * p + 1][0], b[2 * p + 1][1], addr);
            }
#pragma unroll
            for (int mf = 0; mf < 4; mf++)
#pragma unroll
                for (int nf = 0; nf < 4; nf++)
                    mma_f16_16n8k16(acc[mf][nf][0], acc[mf][nf][1],
                                    acc[mf][nf][2], acc[mf][nf][3],
                                    a[mf][0], a[mf][1], a[mf][2], a[mf][3],
                                    b[nf][0], b[nf][1]);
        }
    }

#pragma unroll
    for (int mf = 0; mf < 4; mf++) {
        int row0 = bm + am0 + mf * 16 + gid;
        size_t ro0 = (size_t)row0 * N;
        size_t ro1 = ro0 + (size_t)8 * N;
#pragma unroll
        for (int nf = 0; nf < 4; nf++) {
            int col = bn + bn0 + nf * 8 + tig * 2;
            float2 v0 = make_float2(acc[mf][nf][0], acc[mf][nf][1]);
            float2 v1 = make_float2(acc[mf][nf][2], acc[mf][nf][3]);
            if (add1) {
                float2 t0 = *(const float2*)(add1 + ro0 + col);
                float2 t1 = *(const float2*)(add1 + ro1 + col);
                v0.x += t0.x; v0.y += t0.y; v1.x += t1.x; v1.y += t1.y;
            }
            if (add2h) {
                float2 t0 = __half22float2(*(const __half2*)(add2h + ro0 + col));
                float2 t1 = __half22float2(*(const __half2*)(add2h + ro1 + col));
                v0.x += t0.x; v0.y += t0.y; v1.x += t1.x; v1.y += t1.y;
            }
            *(float2*)(C + ro0 + col) = v0;
            *(float2*)(C + ro1 + col) = v1;
        }
    }
}

// ---------------- convert a weight matrix to fp16 ----------------
__global__ void w_to_h(const float* __restrict__ in, __half* __restrict__ out, int n4)
{
    int i = blockIdx.x * blockDim.x + threadIdx.x;
    if (i >= n4) return;
    float4 v = ((const float4*)in)[i];
    ((__half2*)out)[i * 2]     = __floats2half2_rn(v.x, v.y);
    ((__half2*)out)[i * 2 + 1] = __floats2half2_rn(v.z, v.w);
}

// ---------------- block reduction (sum of two values) ----------------
__device__ __forceinline__ void block_reduce2(float& a, float& b, float* sh)
{
    __syncthreads();
#pragma unroll
    for (int o = 16; o > 0; o >>= 1) {
        a += __shfl_xor_sync(0xffffffffu, a, o);
        b += __shfl_xor_sync(0xffffffffu, b, o);
    }
    int warp = threadIdx.x >> 5, lane = threadIdx.x & 31;
    if (lane == 0) { sh[warp] = a; sh[8 + warp] = b; }
    __syncthreads();
    if (threadIdx.x < 32) {
        float aa = (lane < 8) ? sh[lane] : 0.f;
        float bb = (lane < 8) ? sh[8 + lane] : 0.f;
#pragma unroll
        for (int o = 4; o > 0; o >>= 1) {
            aa += __shfl_xor_sync(0xffffffffu, aa, o);
            bb += __shfl_xor_sync(0xffffffffu, bb, o);
        }
        if (lane == 0) { sh[16] = aa; sh[17] = bb; }
    }
    __syncthreads();
    a = sh[16]; b = sh[17];
}

__device__ __forceinline__ float hsum4(float4 v) { return v.x + v.y + v.z + v.w; }
__device__ __forceinline__ float hsq4(float4 v)  { return v.x*v.x + v.y*v.y + v.z*v.z + v.w*v.w; }

// ---------------- LN stats: one warp per row ----------------
__global__ void __launch_bounds__(256) ln_stats_kernel(const float* __restrict__ x,
                                                       float* __restrict__ mu,
                                                       float* __restrict__ iv)
{
    int warp = threadIdx.x >> 5, lane = threadIdx.x & 31;
    size_t row = (size_t)blockIdx.x * 8 + warp;
    const float4* xr = (const float4*)(x + row * Dd);
    float s = 0.f, s2 = 0.f;
#pragma unroll
    for (int i = 0; i < 16; i++) {
        float4 v = xr[lane + i * 32];
        s += hsum4(v); s2 += hsq4(v);
    }
#pragma unroll
    for (int o = 16; o > 0; o >>= 1) {
        s += __shfl_xor_sync(0xffffffffu, s, o);
        s2 += __shfl_xor_sync(0xffffffffu, s2, o);
    }
    if (lane == 0) {
        float m = s * (1.f / Dd);
        mu[row] = m;
        iv[row] = rsqrtf(s2 * (1.f / Dd) - m * m + 1e-5f);
    }
}

// ---------------- cos/sin of sheaf thetas ----------------
__global__ void sheaf_cs_kernel(const float* __restrict__ th,
                                float* __restrict__ c, float* __restrict__ s)
{
    int i = blockIdx.x * blockDim.x + threadIdx.x;
    if (i < 4 * DH) { float t = th[i]; c[i] = cosf(t); s[i] = sinf(t); }
}

// ------ sheaf fused with LN (via stats): pre = LN(x) - |alpha|*lap, stored fp16 ------
__global__ void __launch_bounds__(256) sheaf_pre_kernel(const float* __restrict__ x,
                                                        __half* __restrict__ preh,
                                                        const float* __restrict__ mu,
                                                        const float* __restrict__ iv,
                                                        const float* __restrict__ lnw,
                                                        const float* __restrict__ lnb,
                                                        const float* __restrict__ cs,
                                                        const float* __restrict__ sn,
                                                        const float* __restrict__ alpha_p)
{
    int row = blockIdx.x;
    int b = row / Tt, t = row % Tt;
    float a = fabsf(alpha_p[0]);
    int j = threadIdx.x;
    float4 w0 = ((const float4*)lnw)[j], w1 = ((const float4*)lnw)[j + 256];
    float4 b0 = ((const float4*)lnb)[j], b1 = ((const float4*)lnb)[j + 256];

    // self LN
    float m_s = mu[row], iv_s = iv[row];
    const float4* xr = (const float4*)(x + (size_t)row * Dd);
    float4 rw = xr[j], rw1 = xr[j + 256];
    float4 xre = make_float4((rw.x - m_s) * iv_s * w0.x + b0.x, (rw.y - m_s) * iv_s * w0.y + b0.y,
                             (rw.z - m_s) * iv_s * w0.z + b0.z, (rw.w - m_s) * iv_s * w0.w + b0.w);
    float4 xim = make_float4((rw1.x - m_s) * iv_s * w1.x + b1.x, (rw1.y - m_s) * iv_s * w1.y + b1.y,
                             (rw1.z - m_s) * iv_s * w1.z + b1.z, (rw1.w - m_s) * iv_s * w1.w + b1.w);
    float4 lr = make_float4(4.f * xre.x, 4.f * xre.y, 4.f * xre.z, 4.f * xre.w);
    float4 li = make_float4(4.f * xim.x, 4.f * xim.y, 4.f * xim.z, 4.f * xim.w);
#pragma unroll
    for (int idx = 0; idx < 4; idx++) {
        int tn = t + (idx - 3);
        float4 yr = make_float4(0.f, 0.f, 0.f, 0.f), yi = yr;
        if (tn >= 0) {
            size_t rn = (size_t)b * Tt + tn;
            float m_n = mu[rn], iv_n = iv[rn];
            const float4* y = (const float4*)(x + rn * Dd);
            float4 v0 = y[j], v1 = y[j + 256];
            yr = make_float4((v0.x - m_n) * iv_n * w0.x + b0.x, (v0.y - m_n) * iv_n * w0.y + b0.y,
                             (v0.z - m_n) * iv_n * w0.z + b0.z, (v0.w - m_n) * iv_n * w0.w + b0.w);
            yi = make_float4((v1.x - m_n) * iv_n * w1.x + b1.x, (v1.y - m_n) * iv_n * w1.y + b1.y,
                             (v1.z - m_n) * iv_n * w1.z + b1.z, (v1.w - m_n) * iv_n * w1.w + b1.w);
        }
        float4 c = ((const float4*)cs)[idx * 256 + j];
        float4 ss = ((const float4*)sn)[idx * 256 + j];
        lr.x -= yr.x * c.x + yi.x * ss.x;  li.x -= yi.x * c.x - yr.x * ss.x;
        lr.y -= yr.y * c.y + yi.y * ss.y;  li.y -= yi.y * c.y - yr.y * ss.y;
        lr.z -= yr.z * c.z + yi.z * ss.z;  li.z -= yi.z * c.z - yr.z * ss.z;
        lr.w -= yr.w * c.w + yi.w * ss.w;  li.w -= yi.w * c.w - yr.w * ss.w;
    }
    __half2* pr = (__half2*)(preh + (size_t)row * Dd);
    pr[j * 2]           = __floats2half2_rn(xre.x - a * lr.x, xre.y - a * lr.y);
    pr[j * 2 + 1]       = __floats2half2_rn(xre.z - a * lr.z, xre.w - a * lr.w);
    pr[512 + j * 2]     = __floats2half2_rn(xim.x - a * li.x, xim.y - a * li.y);
    pr[512 + j * 2 + 1] = __floats2half2_rn(xim.z - a * li.z, xim.w - a * li.w);
}

// ---------------- gist angle cos/sin per (batch, dh) ----------------
__global__ void gist_cs_kernel(const float* __restrict__ gt,
                               const float* __restrict__ gm,
                               const float* __restrict__ gw,
                               const float* __restrict__ strength,
                               float* __restrict__ c, float* __restrict__ s)
{
    int i = blockIdx.x * blockDim.x + threadIdx.x;
    if (i >= Bb * DH) return;
    int b = i / DH, j = i % DH;
    float sig = 1.f / (1.f + expf(-strength[0]));
    float wsum = 0.f, th = 0.f;
#pragma unroll
    for (int k = 0; k < KK; k++) {
        float w = gw[b * KK + k] * gm[b * KK + k];
        wsum += w;
        th += w * gt[(size_t)(b * KK + k) * DH + j];
    }
    th = th / (wsum + 1e-8f) * sig;
    c[i] = cosf(th); s[i] = sinf(th);
}

// ---- fused: xn=LN(x); rot=rotate(xn); x += LN(rot)-xn; y = fp16(LN_gca(x_new)) ----
__global__ void __launch_bounds__(256) gist_fused_kernel(float* __restrict__ x,
    __half* __restrict__ y,
    const float* __restrict__ lnw, const float* __restrict__ lnb,
    const float* __restrict__ grw, const float* __restrict__ grb,
    const float* __restrict__ gcw, const float* __restrict__ gcb,
    const float* __restrict__ gc, const float* __restrict__ gs)
{
    __shared__ float sh[32];
    size_t row = blockIdx.x;
    int b = blockIdx.x / Tt;
    int tid = threadIdx.x;
    float4* xr = (float4*)(x + row * Dd);
    float4 v0 = xr[tid], v1 = xr[tid + 256];
    float s = hsum4(v0) + hsum4(v1);
    float s2 = hsq4(v0) + hsq4(v1);
    block_reduce2(s, s2, sh);
    float mu = s * (1.f / Dd);
    float inv = rsqrtf(s2 * (1.f / Dd) - mu * mu + 1e-5f);
    float4 w0 = ((const float4*)lnw)[tid], w1 = ((const float4*)lnw)[tid + 256];
    float4 bb0 = ((const float4*)lnb)[tid], bb1 = ((const float4*)lnb)[tid + 256];
    float4 xn0 = make_float4((v0.x - mu) * inv * w0.x + bb0.x, (v0.y - mu) * inv * w0.y + bb0.y,
                             (v0.z - mu) * inv * w0.z + bb0.z, (v0.w - mu) * inv * w0.w + bb0.w);
    float4 xn1 = make_float4((v1.x - mu) * inv * w1.x + bb1.x, (v1.y - mu) * inv * w1.y + bb1.y,
                             (v1.z - mu) * inv * w1.z + bb1.z, (v1.w - mu) * inv * w1.w + bb1.w);
    float4 c = ((const float4*)gc)[b * 256 + tid];
    float4 sn = ((const float4*)gs)[b * 256 + tid];
    float4 r0 = make_float4(xn0.x * c.x - xn1.x * sn.x, xn0.y * c.y - xn1.y * sn.y,
                            xn0.z * c.z - xn1.z * sn.z, xn0.w * c.w - xn1.w * sn.w);
    float4 r1 = make_float4(xn0.x * sn.x + xn1.x * c.x, xn0.y * sn.y + xn1.y * c.y,
                            xn0.z * sn.z + xn1.z * c.z, xn0.w * sn.w + xn1.w * c.w);
    float rs = hsum4(r0) + hsum4(r1);
    float rs2 = hsq4(r0) + hsq4(r1);
    block_reduce2(rs, rs2, sh);
    float mu2 = rs * (1.f / Dd);
    float inv2 = rsqrtf(rs2 * (1.f / Dd) - mu2 * mu2 + 1e-5f);
    float4 g0 = ((const float4*)grw)[tid], g1 = ((const float4*)grw)[tid + 256];
    float4 gb0 = ((const float4*)grb)[tid], gb1 = ((const float4*)grb)[tid + 256];
    float4 f0 = make_float4(v0.x + ((r0.x - mu2) * inv2 * g0.x + gb0.x) - xn0.x,
                            v0.y + ((r0.y - mu2) * inv2 * g0.y + gb0.y) - xn0.y,
                            v0.z + ((r0.z - mu2) * inv2 * g0.z + gb0.z) - xn0.z,
                            v0.w + ((r0.w - mu2) * inv2 * g0.w + gb0.w) - xn0.w);
    float4 f1 = make_float4(v1.x + ((r1.x - mu2) * inv2 * g1.x + gb1.x) - xn1.x,
                            v1.y + ((r1.y - mu2) * inv2 * g1.y + gb1.y) - xn1.y,
                            v1.z + ((r1.z - mu2) * inv2 * g1.z + gb1.z) - xn1.z,
                            v1.w + ((r1.w - mu2) * inv2 * g1.w + gb1.w) - xn1.w);
    float fs = hsum4(f0) + hsum4(f1);
    float fs2 = hsq4(f0) + hsq4(f1);
    block_reduce2(fs, fs2, sh);
    float mu3 = fs * (1.f / Dd);
    float inv3 = rsqrtf(fs2 * (1.f / Dd) - mu3 * mu3 + 1e-5f);
    float4 q0 = ((const float4*)gcw)[tid], q1 = ((const float4*)gcw)[tid + 256];
    float4 qb0 = ((const float4*)gcb)[tid], qb1 = ((const float4*)gcb)[tid + 256];
    xr[tid] = f0; xr[tid + 256] = f1;
    __half2* yr = (__half2*)(y + row * Dd);
    yr[tid * 2]           = __floats2half2_rn((f0.x - mu3) * inv3 * q0.x + qb0.x,
                                              (f0.y - mu3) * inv3 * q0.y + qb0.y);
    yr[tid * 2 + 1]       = __floats2half2_rn((f0.z - mu3) * inv3 * q0.z + qb0.z,
                                              (f0.w - mu3) * inv3 * q0.w + qb0.w);
    yr[512 + tid * 2]     = __floats2half2_rn((f1.x - mu3) * inv3 * q1.x + qb1.x,
                                              (f1.y - mu3) * inv3 * q1.y + qb1.y);
    yr[512 + tid * 2 + 1] = __floats2half2_rn((f1.z - mu3) * inv3 * q1.z + qb1.z,
                                              (f1.w - mu3) * inv3 * q1.w + qb1.w);
}

// ---------------- pack concat([gist_theta, gist_mag]) into [64, KPAD] ----------------
__global__ void pack_gist_in(const float* __restrict__ gt, const float* __restrict__ gm,
                             float* __restrict__ out)
{
    int i = blockIdx.x * blockDim.x + threadIdx.x;
    if (i >= 64 * KPAD) return;
    int r = i / KPAD, f = i % KPAD;
    float v = 0.f;
    if (f < DH) v = gt[(size_t)r * DH + f];
    else if (f == DH) v = gm[r];
    out[i] = v;
}

__global__ void pad_W_kernel(const float* __restrict__ W, float* __restrict__ out)
{
    int i = blockIdx.x * blockDim.x + threadIdx.x;
    if (i >= Dd * KPAD) return;
    int o = i / KPAD, f = i % KPAD;
    out[i] = (f < DH + 1) ? W[(size_t)o * (DH + 1) + f] : 0.f;
}

// ---------------- split-K SIMT GEMM for M=64 ----------------
__global__ void __launch_bounds__(256) splitk_nt(const float* __restrict__ A,
                                                 const float* __restrict__ W,
                                                 float* __restrict__ part,
                                                 int M, int N, int Ktot, int Kchunk)
{
    __shared__ float As[2][8][128];
    __shared__ float Bs[2][8][128];
    const int tid = threadIdx.x;
    const int bn = blockIdx.x * 128;
    const int kofs = blockIdx.y * Kchunk;
    const int lrow = tid >> 1;
    const int lcol = (tid & 1) << 2;
    const int tx = tid & 15;
    const int ty = tid >> 4;
    const int tm0 = ty * 8, tn0 = tx * 8;

    const float* Aptr = A + (size_t)lrow * Ktot + kofs + lcol;
    const float* Wptr = W + (size_t)(bn + lrow) * Ktot + kofs + lcol;
    const bool a_ok = lrow < M;

    float acc[8][8];
#pragma unroll
    for (int i = 0; i < 8; i++)
#pragma unroll
        for (int j = 0; j < 8; j++) acc[i][j] = 0.f;

    float4 pa = a_ok ? *(const float4*)Aptr : make_float4(0.f, 0.f, 0.f, 0.f);
    float4 pb = *(const float4*)Wptr;
    As[0][lcol + 0][lrow] = pa.x; As[0][lcol + 1][lrow] = pa.y;
    As[0][lcol + 2][lrow] = pa.z; As[0][lcol + 3][lrow] = pa.w;
    Bs[0][lcol + 0][lrow] = pb.x; Bs[0][lcol + 1][lrow] = pb.y;
    Bs[0][lcol + 2][lrow] = pb.z; Bs[0][lcol + 3][lrow] = pb.w;
    __syncthreads();

    const int ntiles = Kchunk >> 3;
    for (int kt = 0; kt < ntiles; kt++) {
        int buf = kt & 1;
        if (kt + 1 < ntiles) {
            pa = a_ok ? *(const float4*)(Aptr + (size_t)(kt + 1) * 8)
                      : make_float4(0.f, 0.f, 0.f, 0.f);
            pb = *(const float4*)(Wptr + (size_t)(kt + 1) * 8);
        }
#pragma unroll
        for (int k = 0; k < 8; k++) {
            float4 a0 = *(const float4*)&As[buf][k][tm0];
            float4 a1 = *(const float4*)&As[buf][k][tm0 + 4];
            float4 b0 = *(const float4*)&Bs[buf][k][tn0];
            float4 b1 = *(const float4*)&Bs[buf][k][tn0 + 4];
            float af[8] = {a0.x, a0.y, a0.z, a0.w, a1.x, a1.y, a1.z, a1.w};
            float bf[8] = {b0.x, b0.y, b0.z, b0.w, b1.x, b1.y, b1.z, b1.w};
#pragma unroll
            for (int i = 0; i < 8; i++)
#pragma unroll
                for (int j = 0; j < 8; j++)
                    acc[i][j] += af[i] * bf[j];
        }
        if (kt + 1 < ntiles) {
            int nb = buf ^ 1;
            As[nb][lcol + 0][lrow] = pa.x; As[nb][lcol + 1][lrow] = pa.y;
            As[nb][lcol + 2][lrow] = pa.z; As[nb][lcol + 3][lrow] = pa.w;
            Bs[nb][lcol + 0][lrow] = pb.x; Bs[nb][lcol + 1][lrow] = pb.y;
            Bs[nb][lcol + 2][lrow] = pb.z; Bs[nb][lcol + 3][lrow] = pb.w;
            __syncthreads();
        }
    }

    float* po = part + (size_t)blockIdx.y * M * N;
#pragma unroll
    for (int i = 0; i < 8; i++) {
        int gm = tm0 + i;
        if (gm < M) {
#pragma unroll
            for (int j = 0; j < 8; j += 4) {
                int gn = bn + tn0 + j;
                float4 v = make_float4(acc[i][j], acc[i][j + 1], acc[i][j + 2], acc[i][j + 3]);
                *(float4*)(po + (size_t)gm * N + gn) = v;
            }
        }
    }
}

// ---------------- reduce split-K partials (+optional bias) ----------------
__global__ void reduce_part(const float* __restrict__ part, float* __restrict__ C,
                            const float* __restrict__ bias, int MN, int N)
{
    int i = blockIdx.x * blockDim.x + threadIdx.x;
    if (i >= MN) return;
    float s = bias ? bias[i % N] : 0.f;
#pragma unroll
    for (int sp = 0; sp < NSPLIT; sp++) s += part[(size_t)sp * MN + i];
    C[i] = s;
}

// -------- KW[b][h*16+k][i] = fp16( (1/sqrt(128)) * sum_d Kh[b*16+k][h*128+d] * Wq[h*128+d][i] ) --------
__global__ void __launch_bounds__(256) kw_kernel(const float* __restrict__ Kh,
                                                 const float* __restrict__ Wq,
                                                 __half* __restrict__ KW)
{
    __shared__ float Khs[KK][HD];
    const int b = blockIdx.x >> 4, h = blockIdx.x & 15;
    const int tid = threadIdx.x;
    const int i = blockIdx.y * 256 + tid;
#pragma unroll
    for (int j = 0; j < 8; j++) {
        int e = tid + j * 256;
        int k = e >> 7, d = e & 127;
        Khs[k][d] = Kh[(size_t)(b * KK + k) * Dd + h * HD + d];
    }
    __syncthreads();
    float acc[KK];
#pragma unroll
    for (int k = 0; k < KK; k++) acc[k] = 0.f;
    const float* wcol = Wq + (size_t)(h * HD) * Dd + i;
    for (int d = 0; d < HD; d++) {
        float w = wcol[(size_t)d * Dd];
#pragma unroll
        for (int k = 0; k < KK; k++) acc[k] += Khs[k][d] * w;
    }
    __half* out = KW + (size_t)b * HK * Dd + (size_t)(h * KK) * Dd + i;
#pragma unroll
    for (int k = 0; k < KK; k++)
        out[(size_t)k * Dd] = __float2half_rn(acc[k] * 0.088388347648318447f);
}

// -------- VWT[b][o][h*16+k] = fp16( sum_d V[b*16+k][h*128+d] * Wo[o][h*128+d] ) --------
__global__ void __launch_bounds__(128) vwt_kernel(const float* __restrict__ V,
                                                  const float* __restrict__ Wo,
                                                  __half* __restrict__ VWT)
{
    __shared__ float Vs[KK][HD];
    const int b = blockIdx.x >> 4, h = blockIdx.x & 15;
    const int tid = threadIdx.x;
    const int o = blockIdx.y * 128 + tid;
#pragma unroll
    for (int j = 0; j < 16; j++) {
        int e = tid + j * 128;
        int k = e >> 7, d = e & 127;
        Vs[k][d] = V[(size_t)(b * KK + k) * Dd + h * HD + d];
    }
    __syncthreads();
    float acc[KK];
#pragma unroll
    for (int k = 0; k < KK; k++) acc[k] = 0.f;
    const float* wrow = Wo + (size_t)o * Dd + h * HD;
#pragma unroll 8
    for (int d4 = 0; d4 < HD / 4; d4++) {
        float4 w = *(const float4*)(wrow + d4 * 4);
#pragma unroll
        for (int k = 0; k < KK; k++) {
            acc[k] += Vs[k][d4 * 4 + 0] * w.x + Vs[k][d4 * 4 + 1] * w.y
                    + Vs[k][d4 * 4 + 2] * w.z + Vs[k][d4 * 4 + 3] * w.w;
        }
    }
    __half2* out = (__half2*)(VWT + (size_t)b * Dd * HK + (size_t)o * HK + h * KK);
#pragma unroll
    for (int k = 0; k < KK / 2; k++)
        out[k] = __floats2half2_rn(acc[2 * k], acc[2 * k + 1]);
}

// -------- softmax over 16 keys per head, fusing split-K score reduce; P in fp16 --------
__global__ void __launch_bounds__(256) softmax_kernel(const float* __restrict__ scorep,
                                                      __half* __restrict__ P)
{
    const int tid = threadIdx.x;
    const size_t row = blockIdx.x * 16 + (tid >> 4);
    const int h = tid & 15;
    float s[KK];
#pragma unroll
    for (int k = 0; k < KK; k++) {
        size_t idx = row * HK + h * KK + k;
        float v = scorep[idx];
#pragma unroll
        for (int sp = 1; sp < SKS; sp++) v += scorep[(size_t)sp * BT * HK + idx];
        s[k] = v;
    }
    float m = s[0];
#pragma unroll
    for (int k = 1; k < KK; k++) m = fmaxf(m, s[k]);
    float sum = 0.f;
#pragma unroll
    for (int k = 0; k < KK; k++) { s[k] = expf(s[k] - m); sum += s[k]; }
    float rinv = 1.f / sum;
#pragma unroll
    for (int k = 0; k < KK; k++)
        P[row * HK + h * KK + k] = __float2half_rn(s[k] * rinv);
}

// ---------------- orchestration ----------------
extern "C" void kernel_launch(void* const* d_in, const int* in_sizes, int n_in,
                              void* d_out, int out_size)
{
    const float* x            = (const float*)d_in[0];
    const float* gist_theta   = (const float*)d_in[1];
    const float* gist_mag     = (const float*)d_in[2];
    const float* gist_weights = (const float*)d_in[3];
    const float* ln_sheaf_w   = (const float*)d_in[4];
    const float* ln_sheaf_b   = (const float*)d_in[5];
    const float* sheaf_thetas = (const float*)d_in[6];
    const float* alpha        = (const float*)d_in[7];
    const float* corr_W       = (const float*)d_in[8];
    const float* ln_gist_w    = (const float*)d_in[9];
    const float* ln_gist_b    = (const float*)d_in[10];
    const float* gist_strength= (const float*)d_in[11];
    const float* gr_ln_w      = (const float*)d_in[12];
    const float* gr_ln_b      = (const float*)d_in[13];
    const float* ln_gca_w     = (const float*)d_in[14];
    const float* ln_gca_b     = (const float*)d_in[15];
    const float* Wq           = (const float*)d_in[16];
    const float* Wk           = (const float*)d_in[17];
    const float* Wv           = (const float*)d_in[18];
    const float* Wo           = (const float*)d_in[19];
    const float* gist_up_W    = (const float*)d_in[20];
    const float* gist_up_b    = (const float*)d_in[21];
    float* out = (float*)d_out;

    float *muP, *ivP, *repr, *Khb, *Vb, *packin, *Wpad, *part, *scorep, *shc, *shs, *gc, *gs;
    __half *S0h, *S1h, *Wh, *KWh, *VWTh, *Ph;
    cudaGetSymbolAddress((void**)&muP, g_mu);
    cudaGetSymbolAddress((void**)&ivP, g_iv);
    cudaGetSymbolAddress((void**)&S0h, g_S0h);
    cudaGetSymbolAddress((void**)&S1h, g_S1h);
    cudaGetSymbolAddress((void**)&Wh, g_Wh);
    cudaGetSymbolAddress((void**)&repr, g_repr);
    cudaGetSymbolAddress((void**)&Khb, g_Kh);
    cudaGetSymbolAddress((void**)&Vb, g_Vv);
    cudaGetSymbolAddress((void**)&packin, g_packin);
    cudaGetSymbolAddress((void**)&Wpad, g_Wpad);
    cudaGetSymbolAddress((void**)&part, g_part);
    cudaGetSymbolAddress((void**)&KWh, g_KWh);
    cudaGetSymbolAddress((void**)&VWTh, g_VWTh);
    cudaGetSymbolAddress((void**)&scorep, g_scorep);
    cudaGetSymbolAddress((void**)&Ph, g_Ph);
    cudaGetSymbolAddress((void**)&shc, g_shc);
    cudaGetSymbolAddress((void**)&shs, g_shs);
    cudaGetSymbolAddress((void**)&gc, g_gc);
    cudaGetSymbolAddress((void**)&gs, g_gs);

    // one-time setup (outside capture: first call is the correctness run)
    static cudaStream_t s1 = nullptr, s2 = nullptr;
    static cudaEvent_t evFork = nullptr, evKV = nullptr, evW = nullptr;
    if (!s1) {
        cudaStreamCreateWithFlags(&s1, cudaStreamNonBlocking);
        cudaStreamCreateWithFlags(&s2, cudaStreamNonBlocking);
        cudaEventCreateWithFlags(&evFork, cudaEventDisableTiming);
        cudaEventCreateWithFlags(&evKV, cudaEventDisableTiming);
        cudaEventCreateWithFlags(&evW, cudaEventDisableTiming);
        cudaFuncSetAttribute(gemm_mma<32>, cudaFuncAttributeMaxDynamicSharedMemorySize,
                             GEMM_MMA_SMEM);
        cudaFuncSetAttribute(gemm_mma<8>, cudaFuncAttributeMaxDynamicSharedMemorySize,
                             GEMM_MMA_SMEM);
        cudaFuncSetAttribute(gemm_mma<4>, cudaFuncAttributeMaxDynamicSharedMemorySize,
                             GEMM_MMA_SMEM);
    }

    dim3 gemm_big(Dd / 128, BT / 128, 1);    // (16, 64)
    dim3 gemm_sc(HK / 128, BT / 128, SKS);   // (2, 64, 4)
    dim3 gemm_out(Dd / 128, BT / 128, 1);    // (16, 64)
    dim3 sk_grid(Dd / 128, NSPLIT);          // (16, 8)
    const int WN4 = Dd * Dd / 4;
    const int MN64 = 64 * Dd;

    cudaEventRecord(evFork, 0);

    // ---- s1: KV-prep chain (independent of the x path) ----
    cudaStreamWaitEvent(s1, evFork, 0);
    pack_gist_in<<<(64 * KPAD + 255) / 256, 256, 0, s1>>>(gist_theta, gist_mag, packin);
    pad_W_kernel<<<(Dd * KPAD + 255) / 256, 256, 0, s1>>>(gist_up_W, Wpad);
    splitk_nt<<<sk_grid, 256, 0, s1>>>(packin, Wpad, part, 64, Dd, KPAD, KPAD / NSPLIT);
    reduce_part<<<(MN64 + 255) / 256, 256, 0, s1>>>(part, repr, gist_up_b, MN64, Dd);
    splitk_nt<<<sk_grid, 256, 0, s1>>>(repr, Wk, part, 64, Dd, Dd, Dd / NSPLIT);
    reduce_part<<<(MN64 + 255) / 256, 256, 0, s1>>>(part, Khb, nullptr, MN64, Dd);
    splitk_nt<<<sk_grid, 256, 0, s1>>>(repr, Wv, part, 64, Dd, Dd, Dd / NSPLIT);
    reduce_part<<<(MN64 + 255) / 256, 256, 0, s1>>>(part, Vb, nullptr, MN64, Dd);
    kw_kernel<<<dim3(Bb * NH, Dd / 256), 256, 0, s1>>>(Khb, Wq, KWh);
    vwt_kernel<<<dim3(Bb * NH, Dd / 128), 128, 0, s1>>>(Vb, Wo, VWTh);
    cudaEventRecord(evKV, s1);

    // ---- s2: corr_W fp16 conversion ----
    cudaStreamWaitEvent(s2, evFork, 0);
    w_to_h<<<(WN4 + 255) / 256, 256, 0, s2>>>(corr_W, Wh, WN4);
    cudaEventRecord(evW, s2);

    // ---- main stream: stage 1 (sheaf, LN fused via stats) ----
    sheaf_cs_kernel<<<(4 * DH + 255) / 256, 256>>>(sheaf_thetas, shc, shs);
    gist_cs_kernel<<<(Bb * DH + 255) / 256, 256>>>(gist_theta, gist_mag, gist_weights,
                                                   gist_strength, gc, gs);
    ln_stats_kernel<<<BT / 8, 256>>>(x, muP, ivP);
    sheaf_pre_kernel<<<BT, 256>>>(x, S1h, muP, ivP, ln_sheaf_w, ln_sheaf_b,
                                  shc, shs, alpha);
    cudaStreamWaitEvent(0, evW, 0);
    // out = x + pre + pre @ corr_W^T   (fp16 MMA, fp32 accum)
    gemm_mma<32><<<gemm_big, 256, GEMM_MMA_SMEM>>>(S1h, Wh, out, x, S1h, Dd, Dd, 0, 0);

    // ---- stage 2: gist rotation (also emits S0h = fp16(LN_gca(out))) ----
    gist_fused_kernel<<<BT, 256>>>(out, S0h, ln_gist_w, ln_gist_b, gr_ln_w, gr_ln_b,
                                   ln_gca_w, ln_gca_b, gc, gs);

    // ---- join, then attention tail ----
    cudaStreamWaitEvent(0, evKV, 0);
    gemm_mma<8><<<gemm_sc, 256, GEMM_MMA_SMEM>>>(S0h, KWh, scorep, nullptr, nullptr,
                                                 HK, Dd,
                                                 (size_t)HK * Dd, (size_t)BT * HK);
    softmax_kernel<<<BT / 16, 256>>>(scorep, Ph);
    gemm_mma<4><<<gemm_out, 256, GEMM_MMA_SMEM>>>(Ph, VWTh, out, out, nullptr,
                                                  Dd, HK,
                                                  (size_t)Dd * HK, 0);
}

// round 12
// speedup vs baseline: 1.0192x; 1.0192x over previous
#include <cuda_runtime.h>
#include <cuda_fp16.h>
#include <math.h>
#include <stdint.h>

// Problem constants
#define Bb 4
#define Tt 2048
#define Dd 2048
#define DH 1024
#define KK 16
#define NH 16
#define HD 128
#define BT (Bb*Tt)          // 8192 rows
#define KPAD 1088
#define NSPLIT 8
#define HK 256              // NH*KK
#define SKS 4               // split-K for scores GEMM

// ---------------- scratch (device globals; no allocation) ----------------
__device__ float  g_S0[(size_t)BT * Dd];        // sheaf LN output (fp32)
__device__ __half g_S0h[(size_t)BT * Dd];       // LN_gca output (fp16)
__device__ __half g_S1h[(size_t)BT * Dd];       // sheaf pre (fp16)
__device__ __half g_Wh[(size_t)Dd * Dd];        // corr_W (fp16)
__device__ float  g_repr[64 * Dd];
__device__ float  g_Kh[64 * Dd];
__device__ float  g_Vv[64 * Dd];
__device__ float  g_packin[64 * KPAD];
__device__ float  g_Wpad[Dd * KPAD];
__device__ float  g_part[NSPLIT * 64 * Dd];
__device__ __half g_KWh[(size_t)Bb * HK * Dd];  // [b][hk][i]
__device__ __half g_VWTh[(size_t)Bb * Dd * HK]; // [b][o][hk]
__device__ float  g_scorep[(size_t)SKS * BT * HK];
__device__ __half g_Ph[(size_t)BT * HK];
__device__ float  g_shc[4 * DH];
__device__ float  g_shs[4 * DH];
__device__ float  g_gc[Bb * DH];
__device__ float  g_gs[Bb * DH];

// ---------------- helpers ----------------
__device__ __forceinline__ uint32_t smem_u32(const void* p) {
    uint32_t a;
    asm("{ .reg .u64 t; cvta.to.shared.u64 t, %1; cvt.u32.u64 %0, t; }" : "=r"(a) : "l"(p));
    return a;
}
__device__ __forceinline__ void cp16(uint32_t dst, const void* src) {
    asm volatile("cp.async.cg.shared.global [%0], [%1], 16;" :: "r"(dst), "l"(src));
}
__device__ __forceinline__ void ldsm_x4(uint32_t& r0, uint32_t& r1, uint32_t& r2, uint32_t& r3,
                                        uint32_t addr) {
    asm volatile("ldmatrix.sync.aligned.m8n8.x4.b16 {%0,%1,%2,%3}, [%4];"
                 : "=r"(r0), "=r"(r1), "=r"(r2), "=r"(r3) : "r"(addr));
}
__device__ __forceinline__ void mma_f16_16n8k16(float& c0, float& c1, float& c2, float& c3,
                                                uint32_t a0, uint32_t a1, uint32_t a2, uint32_t a3,
                                                uint32_t b0, uint32_t b1) {
    asm volatile(
        "mma.sync.aligned.m16n8k16.row.col.f32.f16.f16.f32 "
        "{%0,%1,%2,%3}, {%4,%5,%6,%7}, {%8,%9}, {%0,%1,%2,%3};"
        : "+f"(c0), "+f"(c1), "+f"(c2), "+f"(c3)
        : "r"(a0), "r"(a1), "r"(a2), "r"(a3), "r"(b0), "r"(b1));
}

// ============== fp16 warp-MMA NT GEMM: C(+add1 fp32)(+add2 fp16) = A @ W^T ==============
// A: [M,Kstride] fp16 row-major, W: [N,Kstride] fp16 row-major (batched by bm>>11 via wbstride).
// blockIdx.z selects K-chunk (kofs = z*Kchunk halfs) and C slab (z*czstride).
// 128x128 tile, 8 warps 2x4 (warp 64x32), K-chunk 64 halfs (128B rows), 3-stage cp.async.
#define KC 64
#define HALF_STAGE 16384
#define STAGE_BYTES 32768
#define NSTAGE 3
#define GEMM_MMA_SMEM (NSTAGE * STAGE_BYTES)   // 98304

__global__ void __launch_bounds__(256, 2) gemm_mma(const __half* __restrict__ A,
                                                   const __half* __restrict__ W,
                                                   float* __restrict__ C,
                                                   const float* __restrict__ add1,
                                                   const __half* __restrict__ add2h,
                                                   int N, int Kstride, int Kchunk,
                                                   size_t wbstride, size_t czstride)
{
    extern __shared__ char dyn[];
    const int tid = threadIdx.x;
    const int bm = blockIdx.y * 128;
    const int bn = blockIdx.x * 128;
    const int kofs = blockIdx.z * Kchunk;
    const int nt = Kchunk / KC;

    const int lane = tid & 31, wid = tid >> 5;
    const int wm = wid & 1, wn = wid >> 1;
    const int gid = lane >> 2, tig = lane & 3;
    const int am0 = wm * 64;
    const int bn0 = wn * 32;

    const uint32_t tile0 = smem_u32(dyn);
    const __half* Abase = A + (size_t)bm * Kstride + kofs;
    const __half* Wbase = W + (size_t)(bm >> 11) * wbstride + (size_t)bn * Kstride + kofs;
    C += (size_t)blockIdx.z * czstride;

    const int lrow = lane & 7, lmat = lane >> 3;
    uint32_t aoff[4]; int arm[4];
#pragma unroll
    for (int mf = 0; mf < 4; mf++) {
        int r = am0 + mf * 16 + ((lmat & 1) << 3) + lrow;
        aoff[mf] = (uint32_t)(r * 128);
        arm[mf] = r & 7;
    }
    const int achunk_add = lmat >> 1;
    uint32_t boff[2]; int brm[2];
#pragma unroll
    for (int p = 0; p < 2; p++) {
        int r = bn0 + ((p * 2 + (lmat >> 1)) << 3) + lrow;
        boff[p] = (uint32_t)(r * 128);
        brm[p] = r & 7;
    }
    const int bchunk_add = lmat & 1;

    float acc[4][4][4];
#pragma unroll
    for (int i = 0; i < 4; i++)
#pragma unroll
        for (int j = 0; j < 4; j++)
#pragma unroll
            for (int r = 0; r < 4; r++) acc[i][j][r] = 0.f;

    auto load_stage = [&](int kt) {
        uint32_t base = tile0 + (kt % NSTAGE) * STAGE_BYTES;
#pragma unroll
        for (int i = 0; i < 4; i++) {
            int c = i * 256 + tid;               // 0..1023
            int row = c >> 3, ch = c & 7;
            uint32_t dof = (uint32_t)(row * 128 + ((ch ^ (row & 7)) << 4));
            cp16(base + dof,              Abase + (size_t)row * Kstride + kt * KC + ch * 8);
            cp16(base + HALF_STAGE + dof, Wbase + (size_t)row * Kstride + kt * KC + ch * 8);
        }
        asm volatile("cp.async.commit_group;" ::: "memory");
    };

    load_stage(0);
    if (nt > 1) load_stage(1);

    for (int kt = 0; kt < nt; kt++) {
        if (kt + 1 < nt) asm volatile("cp.async.wait_group 1;" ::: "memory");
        else             asm volatile("cp.async.wait_group 0;" ::: "memory");
        __syncthreads();
        if (kt + 2 < nt) load_stage(kt + 2);

        uint32_t As_u = tile0 + (kt % NSTAGE) * STAGE_BYTES;
        uint32_t Bs_u = As_u + HALF_STAGE;
#pragma unroll
        for (int ks = 0; ks < 4; ks++) {        // 4 x k16 per 64-half chunk
            uint32_t a[4][4], b[4][2];
#pragma unroll
            for (int mf = 0; mf < 4; mf++) {
                uint32_t addr = As_u + aoff[mf] +
                                (uint32_t)(((2 * ks + achunk_add) ^ arm[mf]) << 4);
                ldsm_x4(a[mf][0], a[mf][1], a[mf][2], a[mf][3], addr);
            }
#pragma unroll
            for (int p = 0; p < 2; p++) {
                uint32_t addr = Bs_u + boff[p] +
                                (uint32_t)(((2 * ks + bchunk_add) ^ brm[p]) << 4);
                ldsm_x4(b[2 * p][0], b[2 * p][1], b[2 * p + 1][0], b[2 * p + 1][1], addr);
            }
#pragma unroll
            for (int mf = 0; mf < 4; mf++)
#pragma unroll
                for (int nf = 0; nf < 4; nf++)
                    mma_f16_16n8k16(acc[mf][nf][0], acc[mf][nf][1],
                                    acc[mf][nf][2], acc[mf][nf][3],
                                    a[mf][0], a[mf][1], a[mf][2], a[mf][3],
                                    b[nf][0], b[nf][1]);
        }
    }

#pragma unroll
    for (int mf = 0; mf < 4; mf++) {
        int row0 = bm + am0 + mf * 16 + gid;
        size_t ro0 = (size_t)row0 * N;
        size_t ro1 = ro0 + (size_t)8 * N;
#pragma unroll
        for (int nf = 0; nf < 4; nf++) {
            int col = bn + bn0 + nf * 8 + tig * 2;
            float2 v0 = make_float2(acc[mf][nf][0], acc[mf][nf][1]);
            float2 v1 = make_float2(acc[mf][nf][2], acc[mf][nf][3]);
            if (add1) {
                float2 t0 = *(const float2*)(add1 + ro0 + col);
                float2 t1 = *(const float2*)(add1 + ro1 + col);
                v0.x += t0.x; v0.y += t0.y; v1.x += t1.x; v1.y += t1.y;
            }
            if (add2h) {
                float2 t0 = __half22float2(*(const __half2*)(add2h + ro0 + col));
                float2 t1 = __half22float2(*(const __half2*)(add2h + ro1 + col));
                v0.x += t0.x; v0.y += t0.y; v1.x += t1.x; v1.y += t1.y;
            }
            *(float2*)(C + ro0 + col) = v0;
            *(float2*)(C + ro1 + col) = v1;
        }
    }
}

// ---------------- convert a weight matrix to fp16 ----------------
__global__ void w_to_h(const float* __restrict__ in, __half* __restrict__ out, int n4)
{
    int i = blockIdx.x * blockDim.x + threadIdx.x;
    if (i >= n4) return;
    float4 v = ((const float4*)in)[i];
    ((__half2*)out)[i * 2]     = __floats2half2_rn(v.x, v.y);
    ((__half2*)out)[i * 2 + 1] = __floats2half2_rn(v.z, v.w);
}

// ---------------- block reduction (sum of two values) ----------------
__device__ __forceinline__ void block_reduce2(float& a, float& b, float* sh)
{
    __syncthreads();
#pragma unroll
    for (int o = 16; o > 0; o >>= 1) {
        a += __shfl_xor_sync(0xffffffffu, a, o);
        b += __shfl_xor_sync(0xffffffffu, b, o);
    }
    int warp = threadIdx.x >> 5, lane = threadIdx.x & 31;
    if (lane == 0) { sh[warp] = a; sh[8 + warp] = b; }
    __syncthreads();
    if (threadIdx.x < 32) {
        float aa = (lane < 8) ? sh[lane] : 0.f;
        float bb = (lane < 8) ? sh[8 + lane] : 0.f;
#pragma unroll
        for (int o = 4; o > 0; o >>= 1) {
            aa += __shfl_xor_sync(0xffffffffu, aa, o);
            bb += __shfl_xor_sync(0xffffffffu, bb, o);
        }
        if (lane == 0) { sh[16] = aa; sh[17] = bb; }
    }
    __syncthreads();
    a = sh[16]; b = sh[17];
}

__device__ __forceinline__ float hsum4(float4 v) { return v.x + v.y + v.z + v.w; }
__device__ __forceinline__ float hsq4(float4 v)  { return v.x*v.x + v.y*v.y + v.z*v.z + v.w*v.w; }

// ---------------- LayerNorm (fp32 out; sheaf path) ----------------
__global__ void __launch_bounds__(256) ln_kernel(const float* __restrict__ x,
                                                 float* __restrict__ y,
                                                 const float* __restrict__ w,
                                                 const float* __restrict__ b)
{
    __shared__ float sh[32];
    size_t row = blockIdx.x;
    const float4* xr = (const float4*)(x + row * Dd);
    int tid = threadIdx.x;
    float4 v0 = xr[tid], v1 = xr[tid + 256];
    float s = hsum4(v0) + hsum4(v1);
    float s2 = hsq4(v0) + hsq4(v1);
    block_reduce2(s, s2, sh);
    float mu = s * (1.f / Dd);
    float inv = rsqrtf(s2 * (1.f / Dd) - mu * mu + 1e-5f);
    float4 w0 = ((const float4*)w)[tid], w1 = ((const float4*)w)[tid + 256];
    float4 b0 = ((const float4*)b)[tid], b1 = ((const float4*)b)[tid + 256];
    float4* yr = (float4*)(y + row * Dd);
    yr[tid] = make_float4((v0.x - mu) * inv * w0.x + b0.x, (v0.y - mu) * inv * w0.y + b0.y,
                          (v0.z - mu) * inv * w0.z + b0.z, (v0.w - mu) * inv * w0.w + b0.w);
    yr[tid + 256] = make_float4((v1.x - mu) * inv * w1.x + b1.x, (v1.y - mu) * inv * w1.y + b1.y,
                                (v1.z - mu) * inv * w1.z + b1.z, (v1.w - mu) * inv * w1.w + b1.w);
}

// ---------------- cos/sin of sheaf thetas ----------------
__global__ void sheaf_cs_kernel(const float* __restrict__ th,
                                float* __restrict__ c, float* __restrict__ s)
{
    int i = blockIdx.x * blockDim.x + threadIdx.x;
    if (i < 4 * DH) { float t = th[i]; c[i] = cosf(t); s[i] = sinf(t); }
}

// ---------------- sheaf: pre = xln - |alpha| * lap, stored fp16 ----------------
__global__ void __launch_bounds__(256) sheaf_pre_kernel(const float* __restrict__ xln,
                                                        __half* __restrict__ preh,
                                                        const float* __restrict__ cs,
                                                        const float* __restrict__ sn,
                                                        const float* __restrict__ alpha_p)
{
    int row = blockIdx.x;
    int b = row / Tt, t = row % Tt;
    float a = fabsf(alpha_p[0]);
    const float4* xr = (const float4*)(xln + (size_t)row * Dd);
    int j = threadIdx.x;
    float4 xre = xr[j], xim = xr[j + 256];
    float4 lr = make_float4(4.f * xre.x, 4.f * xre.y, 4.f * xre.z, 4.f * xre.w);
    float4 li = make_float4(4.f * xim.x, 4.f * xim.y, 4.f * xim.z, 4.f * xim.w);
#pragma unroll
    for (int idx = 0; idx < 4; idx++) {
        int tn = t + (idx - 3);
        float4 yr = make_float4(0.f, 0.f, 0.f, 0.f), yi = yr;
        if (tn >= 0) {
            const float4* y = (const float4*)(xln + ((size_t)b * Tt + tn) * Dd);
            yr = y[j]; yi = y[j + 256];
        }
        float4 c = ((const float4*)cs)[idx * 256 + j];
        float4 ss = ((const float4*)sn)[idx * 256 + j];
        lr.x -= yr.x * c.x + yi.x * ss.x;  li.x -= yi.x * c.x - yr.x * ss.x;
        lr.y -= yr.y * c.y + yi.y * ss.y;  li.y -= yi.y * c.y - yr.y * ss.y;
        lr.z -= yr.z * c.z + yi.z * ss.z;  li.z -= yi.z * c.z - yr.z * ss.z;
        lr.w -= yr.w * c.w + yi.w * ss.w;  li.w -= yi.w * c.w - yr.w * ss.w;
    }
    __half2* pr = (__half2*)(preh + (size_t)row * Dd);
    pr[j * 2]           = __floats2half2_rn(xre.x - a * lr.x, xre.y - a * lr.y);
    pr[j * 2 + 1]       = __floats2half2_rn(xre.z - a * lr.z, xre.w - a * lr.w);
    pr[512 + j * 2]     = __floats2half2_rn(xim.x - a * li.x, xim.y - a * li.y);
    pr[512 + j * 2 + 1] = __floats2half2_rn(xim.z - a * li.z, xim.w - a * li.w);
}

// ---------------- gist angle cos/sin per (batch, dh) ----------------
__global__ void gist_cs_kernel(const float* __restrict__ gt,
                               const float* __restrict__ gm,
                               const float* __restrict__ gw,
                               const float* __restrict__ strength,
                               float* __restrict__ c, float* __restrict__ s)
{
    int i = blockIdx.x * blockDim.x + threadIdx.x;
    if (i >= Bb * DH) return;
    int b = i / DH, j = i % DH;
    float sig = 1.f / (1.f + expf(-strength[0]));
    float wsum = 0.f, th = 0.f;
#pragma unroll
    for (int k = 0; k < KK; k++) {
        float w = gw[b * KK + k] * gm[b * KK + k];
        wsum += w;
        th += w * gt[(size_t)(b * KK + k) * DH + j];
    }
    th = th / (wsum + 1e-8f) * sig;
    c[i] = cosf(th); s[i] = sinf(th);
}

// ---- fused: xn=LN(x); rot=rotate(xn); x += LN(rot)-xn; y = fp16(LN_gca(x_new)) ----
__global__ void __launch_bounds__(256) gist_fused_kernel(float* __restrict__ x,
    __half* __restrict__ y,
    const float* __restrict__ lnw, const float* __restrict__ lnb,
    const float* __restrict__ grw, const float* __restrict__ grb,
    const float* __restrict__ gcw, const float* __restrict__ gcb,
    const float* __restrict__ gc, const float* __restrict__ gs)
{
    __shared__ float sh[32];
    size_t row = blockIdx.x;
    int b = blockIdx.x / Tt;
    int tid = threadIdx.x;
    float4* xr = (float4*)(x + row * Dd);
    float4 v0 = xr[tid], v1 = xr[tid + 256];
    float s = hsum4(v0) + hsum4(v1);
    float s2 = hsq4(v0) + hsq4(v1);
    block_reduce2(s, s2, sh);
    float mu = s * (1.f / Dd);
    float inv = rsqrtf(s2 * (1.f / Dd) - mu * mu + 1e-5f);
    float4 w0 = ((const float4*)lnw)[tid], w1 = ((const float4*)lnw)[tid + 256];
    float4 bb0 = ((const float4*)lnb)[tid], bb1 = ((const float4*)lnb)[tid + 256];
    float4 xn0 = make_float4((v0.x - mu) * inv * w0.x + bb0.x, (v0.y - mu) * inv * w0.y + bb0.y,
                             (v0.z - mu) * inv * w0.z + bb0.z, (v0.w - mu) * inv * w0.w + bb0.w);
    float4 xn1 = make_float4((v1.x - mu) * inv * w1.x + bb1.x, (v1.y - mu) * inv * w1.y + bb1.y,
                             (v1.z - mu) * inv * w1.z + bb1.z, (v1.w - mu) * inv * w1.w + bb1.w);
    float4 c = ((const float4*)gc)[b * 256 + tid];
    float4 sn = ((const float4*)gs)[b * 256 + tid];
    float4 r0 = make_float4(xn0.x * c.x - xn1.x * sn.x, xn0.y * c.y - xn1.y * sn.y,
                            xn0.z * c.z - xn1.z * sn.z, xn0.w * c.w - xn1.w * sn.w);
    float4 r1 = make_float4(xn0.x * sn.x + xn1.x * c.x, xn0.y * sn.y + xn1.y * c.y,
                            xn0.z * sn.z + xn1.z * c.z, xn0.w * sn.w + xn1.w * c.w);
    float rs = hsum4(r0) + hsum4(r1);
    float rs2 = hsq4(r0) + hsq4(r1);
    block_reduce2(rs, rs2, sh);
    float mu2 = rs * (1.f / Dd);
    float inv2 = rsqrtf(rs2 * (1.f / Dd) - mu2 * mu2 + 1e-5f);
    float4 g0 = ((const float4*)grw)[tid], g1 = ((const float4*)grw)[tid + 256];
    float4 gb0 = ((const float4*)grb)[tid], gb1 = ((const float4*)grb)[tid + 256];
    float4 f0 = make_float4(v0.x + ((r0.x - mu2) * inv2 * g0.x + gb0.x) - xn0.x,
                            v0.y + ((r0.y - mu2) * inv2 * g0.y + gb0.y) - xn0.y,
                            v0.z + ((r0.z - mu2) * inv2 * g0.z + gb0.z) - xn0.z,
                            v0.w + ((r0.w - mu2) * inv2 * g0.w + gb0.w) - xn0.w);
    float4 f1 = make_float4(v1.x + ((r1.x - mu2) * inv2 * g1.x + gb1.x) - xn1.x,
                            v1.y + ((r1.y - mu2) * inv2 * g1.y + gb1.y) - xn1.y,
                            v1.z + ((r1.z - mu2) * inv2 * g1.z + gb1.z) - xn1.z,
                            v1.w + ((r1.w - mu2) * inv2 * g1.w + gb1.w) - xn1.w);
    float fs = hsum4(f0) + hsum4(f1);
    float fs2 = hsq4(f0) + hsq4(f1);
    block_reduce2(fs, fs2, sh);
    float mu3 = fs * (1.f / Dd);
    float inv3 = rsqrtf(fs2 * (1.f / Dd) - mu3 * mu3 + 1e-5f);
    float4 q0 = ((const float4*)gcw)[tid], q1 = ((const float4*)gcw)[tid + 256];
    float4 qb0 = ((const float4*)gcb)[tid], qb1 = ((const float4*)gcb)[tid + 256];
    xr[tid] = f0; xr[tid + 256] = f1;
    __half2* yr = (__half2*)(y + row * Dd);
    yr[tid * 2]           = __floats2half2_rn((f0.x - mu3) * inv3 * q0.x + qb0.x,
                                              (f0.y - mu3) * inv3 * q0.y + qb0.y);
    yr[tid * 2 + 1]       = __floats2half2_rn((f0.z - mu3) * inv3 * q0.z + qb0.z,
                                              (f0.w - mu3) * inv3 * q0.w + qb0.w);
    yr[512 + tid * 2]     = __floats2half2_rn((f1.x - mu3) * inv3 * q1.x + qb1.x,
                                              (f1.y - mu3) * inv3 * q1.y + qb1.y);
    yr[512 + tid * 2 + 1] = __floats2half2_rn((f1.z - mu3) * inv3 * q1.z + qb1.z,
                                              (f1.w - mu3) * inv3 * q1.w + qb1.w);
}

// ---------------- pack concat([gist_theta, gist_mag]) into [64, KPAD] ----------------
__global__ void pack_gist_in(const float* __restrict__ gt, const float* __restrict__ gm,
                             float* __restrict__ out)
{
    int i = blockIdx.x * blockDim.x + threadIdx.x;
    if (i >= 64 * KPAD) return;
    int r = i / KPAD, f = i % KPAD;
    float v = 0.f;
    if (f < DH) v = gt[(size_t)r * DH + f];
    else if (f == DH) v = gm[r];
    out[i] = v;
}

__global__ void pad_W_kernel(const float* __restrict__ W, float* __restrict__ out)
{
    int i = blockIdx.x * blockDim.x + threadIdx.x;
    if (i >= Dd * KPAD) return;
    int o = i / KPAD, f = i % KPAD;
    out[i] = (f < DH + 1) ? W[(size_t)o * (DH + 1) + f] : 0.f;
}

// ---------------- split-K SIMT GEMM for M=64 ----------------
__global__ void __launch_bounds__(256) splitk_nt(const float* __restrict__ A,
                                                 const float* __restrict__ W,
                                                 float* __restrict__ part,
                                                 int M, int N, int Ktot, int Kchunk)
{
    __shared__ float As[2][8][128];
    __shared__ float Bs[2][8][128];
    const int tid = threadIdx.x;
    const int bn = blockIdx.x * 128;
    const int kofs = blockIdx.y * Kchunk;
    const int lrow = tid >> 1;
    const int lcol = (tid & 1) << 2;
    const int tx = tid & 15;
    const int ty = tid >> 4;
    const int tm0 = ty * 8, tn0 = tx * 8;

    const float* Aptr = A + (size_t)lrow * Ktot + kofs + lcol;
    const float* Wptr = W + (size_t)(bn + lrow) * Ktot + kofs + lcol;
    const bool a_ok = lrow < M;

    float acc[8][8];
#pragma unroll
    for (int i = 0; i < 8; i++)
#pragma unroll
        for (int j = 0; j < 8; j++) acc[i][j] = 0.f;

    float4 pa = a_ok ? *(const float4*)Aptr : make_float4(0.f, 0.f, 0.f, 0.f);
    float4 pb = *(const float4*)Wptr;
    As[0][lcol + 0][lrow] = pa.x; As[0][lcol + 1][lrow] = pa.y;
    As[0][lcol + 2][lrow] = pa.z; As[0][lcol + 3][lrow] = pa.w;
    Bs[0][lcol + 0][lrow] = pb.x; Bs[0][lcol + 1][lrow] = pb.y;
    Bs[0][lcol + 2][lrow] = pb.z; Bs[0][lcol + 3][lrow] = pb.w;
    __syncthreads();

    const int ntiles = Kchunk >> 3;
    for (int kt = 0; kt < ntiles; kt++) {
        int buf = kt & 1;
        if (kt + 1 < ntiles) {
            pa = a_ok ? *(const float4*)(Aptr + (size_t)(kt + 1) * 8)
                      : make_float4(0.f, 0.f, 0.f, 0.f);
            pb = *(const float4*)(Wptr + (size_t)(kt + 1) * 8);
        }
#pragma unroll
        for (int k = 0; k < 8; k++) {
            float4 a0 = *(const float4*)&As[buf][k][tm0];
            float4 a1 = *(const float4*)&As[buf][k][tm0 + 4];
            float4 b0 = *(const float4*)&Bs[buf][k][tn0];
            float4 b1 = *(const float4*)&Bs[buf][k][tn0 + 4];
            float af[8] = {a0.x, a0.y, a0.z, a0.w, a1.x, a1.y, a1.z, a1.w};
            float bf[8] = {b0.x, b0.y, b0.z, b0.w, b1.x, b1.y, b1.z, b1.w};
#pragma unroll
            for (int i = 0; i < 8; i++)
#pragma unroll
                for (int j = 0; j < 8; j++)
                    acc[i][j] += af[i] * bf[j];
        }
        if (kt + 1 < ntiles) {
            int nb = buf ^ 1;
            As[nb][lcol + 0][lrow] = pa.x; As[nb][lcol + 1][lrow] = pa.y;
            As[nb][lcol + 2][lrow] = pa.z; As[nb][lcol + 3][lrow] = pa.w;
            Bs[nb][lcol + 0][lrow] = pb.x; Bs[nb][lcol + 1][lrow] = pb.y;
            Bs[nb][lcol + 2][lrow] = pb.z; Bs[nb][lcol + 3][lrow] = pb.w;
            __syncthreads();
        }
    }

    float* po = part + (size_t)blockIdx.y * M * N;
#pragma unroll
    for (int i = 0; i < 8; i++) {
        int gm = tm0 + i;
        if (gm < M) {
#pragma unroll
            for (int j = 0; j < 8; j += 4) {
                int gn = bn + tn0 + j;
                float4 v = make_float4(acc[i][j], acc[i][j + 1], acc[i][j + 2], acc[i][j + 3]);
                *(float4*)(po + (size_t)gm * N + gn) = v;
            }
        }
    }
}

// ---------------- reduce split-K partials (+optional bias) ----------------
__global__ void reduce_part(const float* __restrict__ part, float* __restrict__ C,
                            const float* __restrict__ bias, int MN, int N)
{
    int i = blockIdx.x * blockDim.x + threadIdx.x;
    if (i >= MN) return;
    float s = bias ? bias[i % N] : 0.f;
#pragma unroll
    for (int sp = 0; sp < NSPLIT; sp++) s += part[(size_t)sp * MN + i];
    C[i] = s;
}

// -------- KW[b][h*16+k][i] = fp16( (1/sqrt(128)) * sum_d Kh[b*16+k][h*128+d] * Wq[h*128+d][i] ) --------
__global__ void __launch_bounds__(256) kw_kernel(const float* __restrict__ Kh,
                                                 const float* __restrict__ Wq,
                                                 __half* __restrict__ KW)
{
    __shared__ float Khs[KK][HD];
    const int b = blockIdx.x >> 4, h = blockIdx.x & 15;
    const int tid = threadIdx.x;
    const int i = blockIdx.y * 256 + tid;
#pragma unroll
    for (int j = 0; j < 8; j++) {
        int e = tid + j * 256;
        int k = e >> 7, d = e & 127;
        Khs[k][d] = Kh[(size_t)(b * KK + k) * Dd + h * HD + d];
    }
    __syncthreads();
    float acc[KK];
#pragma unroll
    for (int k = 0; k < KK; k++) acc[k] = 0.f;
    const float* wcol = Wq + (size_t)(h * HD) * Dd + i;
    for (int d = 0; d < HD; d++) {
        float w = wcol[(size_t)d * Dd];
#pragma unroll
        for (int k = 0; k < KK; k++) acc[k] += Khs[k][d] * w;
    }
    __half* out = KW + (size_t)b * HK * Dd + (size_t)(h * KK) * Dd + i;
#pragma unroll
    for (int k = 0; k < KK; k++)
        out[(size_t)k * Dd] = __float2half_rn(acc[k] * 0.088388347648318447f);
}

// -------- VWT[b][o][h*16+k] = fp16( sum_d V[b*16+k][h*128+d] * Wo[o][h*128+d] ) --------
__global__ void __launch_bounds__(128) vwt_kernel(const float* __restrict__ V,
                                                  const float* __restrict__ Wo,
                                                  __half* __restrict__ VWT)
{
    __shared__ float Vs[KK][HD];
    const int b = blockIdx.x >> 4, h = blockIdx.x & 15;
    const int tid = threadIdx.x;
    const int o = blockIdx.y * 128 + tid;
#pragma unroll
    for (int j = 0; j < 16; j++) {
        int e = tid + j * 128;
        int k = e >> 7, d = e & 127;
        Vs[k][d] = V[(size_t)(b * KK + k) * Dd + h * HD + d];
    }
    __syncthreads();
    float acc[KK];
#pragma unroll
    for (int k = 0; k < KK; k++) acc[k] = 0.f;
    const float* wrow = Wo + (size_t)o * Dd + h * HD;
#pragma unroll 8
    for (int d4 = 0; d4 < HD / 4; d4++) {
        float4 w = *(const float4*)(wrow + d4 * 4);
#pragma unroll
        for (int k = 0; k < KK; k++) {
            acc[k] += Vs[k][d4 * 4 + 0] * w.x + Vs[k][d4 * 4 + 1] * w.y
                    + Vs[k][d4 * 4 + 2] * w.z + Vs[k][d4 * 4 + 3] * w.w;
        }
    }
    __half2* out = (__half2*)(VWT + (size_t)b * Dd * HK + (size_t)o * HK + h * KK);
#pragma unroll
    for (int k = 0; k < KK / 2; k++)
        out[k] = __floats2half2_rn(acc[2 * k], acc[2 * k + 1]);
}

// -------- softmax over 16 keys per head, fusing split-K score reduce; P in fp16 --------
__global__ void __launch_bounds__(256) softmax_kernel(const float* __restrict__ scorep,
                                                      __half* __restrict__ P)
{
    const int tid = threadIdx.x;
    const size_t row = blockIdx.x * 16 + (tid >> 4);
    const int h = tid & 15;
    float s[KK];
#pragma unroll
    for (int k = 0; k < KK; k++) {
        size_t idx = row * HK + h * KK + k;
        float v = scorep[idx];
#pragma unroll
        for (int sp = 1; sp < SKS; sp++) v += scorep[(size_t)sp * BT * HK + idx];
        s[k] = v;
    }
    float m = s[0];
#pragma unroll
    for (int k = 1; k < KK; k++) m = fmaxf(m, s[k]);
    float sum = 0.f;
#pragma unroll
    for (int k = 0; k < KK; k++) { s[k] = expf(s[k] - m); sum += s[k]; }
    float rinv = 1.f / sum;
#pragma unroll
    for (int k = 0; k < KK; k++)
        P[row * HK + h * KK + k] = __float2half_rn(s[k] * rinv);
}

// ---------------- orchestration ----------------
extern "C" void kernel_launch(void* const* d_in, const int* in_sizes, int n_in,
                              void* d_out, int out_size)
{
    const float* x            = (const float*)d_in[0];
    const float* gist_theta   = (const float*)d_in[1];
    const float* gist_mag     = (const float*)d_in[2];
    const float* gist_weights = (const float*)d_in[3];
    const float* ln_sheaf_w   = (const float*)d_in[4];
    const float* ln_sheaf_b   = (const float*)d_in[5];
    const float* sheaf_thetas = (const float*)d_in[6];
    const float* alpha        = (const float*)d_in[7];
    const float* corr_W       = (const float*)d_in[8];
    const float* ln_gist_w    = (const float*)d_in[9];
    const float* ln_gist_b    = (const float*)d_in[10];
    const float* gist_strength= (const float*)d_in[11];
    const float* gr_ln_w      = (const float*)d_in[12];
    const float* gr_ln_b      = (const float*)d_in[13];
    const float* ln_gca_w     = (const float*)d_in[14];
    const float* ln_gca_b     = (const float*)d_in[15];
    const float* Wq           = (const float*)d_in[16];
    const float* Wk           = (const float*)d_in[17];
    const float* Wv           = (const float*)d_in[18];
    const float* Wo           = (const float*)d_in[19];
    const float* gist_up_W    = (const float*)d_in[20];
    const float* gist_up_b    = (const float*)d_in[21];
    float* out = (float*)d_out;

    float *S0, *repr, *Khb, *Vb, *packin, *Wpad, *part, *scorep, *shc, *shs, *gc, *gs;
    __half *S0h, *S1h, *Wh, *KWh, *VWTh, *Ph;
    cudaGetSymbolAddress((void**)&S0, g_S0);
    cudaGetSymbolAddress((void**)&S0h, g_S0h);
    cudaGetSymbolAddress((void**)&S1h, g_S1h);
    cudaGetSymbolAddress((void**)&Wh, g_Wh);
    cudaGetSymbolAddress((void**)&repr, g_repr);
    cudaGetSymbolAddress((void**)&Khb, g_Kh);
    cudaGetSymbolAddress((void**)&Vb, g_Vv);
    cudaGetSymbolAddress((void**)&packin, g_packin);
    cudaGetSymbolAddress((void**)&Wpad, g_Wpad);
    cudaGetSymbolAddress((void**)&part, g_part);
    cudaGetSymbolAddress((void**)&KWh, g_KWh);
    cudaGetSymbolAddress((void**)&VWTh, g_VWTh);
    cudaGetSymbolAddress((void**)&scorep, g_scorep);
    cudaGetSymbolAddress((void**)&Ph, g_Ph);
    cudaGetSymbolAddress((void**)&shc, g_shc);
    cudaGetSymbolAddress((void**)&shs, g_shs);
    cudaGetSymbolAddress((void**)&gc, g_gc);
    cudaGetSymbolAddress((void**)&gs, g_gs);

    // one-time setup (outside capture: first call is the correctness run)
    static cudaStream_t s1 = nullptr, s2 = nullptr;
    static cudaEvent_t evFork = nullptr, evKV = nullptr, evW = nullptr;
    if (!s1) {
        cudaStreamCreateWithFlags(&s1, cudaStreamNonBlocking);
        cudaStreamCreateWithFlags(&s2, cudaStreamNonBlocking);
        cudaEventCreateWithFlags(&evFork, cudaEventDisableTiming);
        cudaEventCreateWithFlags(&evKV, cudaEventDisableTiming);
        cudaEventCreateWithFlags(&evW, cudaEventDisableTiming);
        cudaFuncSetAttribute(gemm_mma, cudaFuncAttributeMaxDynamicSharedMemorySize,
                             GEMM_MMA_SMEM);
    }

    dim3 gemm_big(Dd / 128, BT / 128, 1);    // (16, 64)
    dim3 gemm_sc(HK / 128, BT / 128, SKS);   // (2, 64, 4)
    dim3 gemm_out(Dd / 128, BT / 128, 1);    // (16, 64)
    dim3 sk_grid(Dd / 128, NSPLIT);          // (16, 8)
    const int WN4 = Dd * Dd / 4;
    const int MN64 = 64 * Dd;

    cudaEventRecord(evFork, 0);

    // ---- s1: KV-prep chain (independent of the x path) ----
    cudaStreamWaitEvent(s1, evFork, 0);
    pack_gist_in<<<(64 * KPAD + 255) / 256, 256, 0, s1>>>(gist_theta, gist_mag, packin);
    pad_W_kernel<<<(Dd * KPAD + 255) / 256, 256, 0, s1>>>(gist_up_W, Wpad);
    splitk_nt<<<sk_grid, 256, 0, s1>>>(packin, Wpad, part, 64, Dd, KPAD, KPAD / NSPLIT);
    reduce_part<<<(MN64 + 255) / 256, 256, 0, s1>>>(part, repr, gist_up_b, MN64, Dd);
    splitk_nt<<<sk_grid, 256, 0, s1>>>(repr, Wk, part, 64, Dd, Dd, Dd / NSPLIT);
    reduce_part<<<(MN64 + 255) / 256, 256, 0, s1>>>(part, Khb, nullptr, MN64, Dd);
    splitk_nt<<<sk_grid, 256, 0, s1>>>(repr, Wv, part, 64, Dd, Dd, Dd / NSPLIT);
    reduce_part<<<(MN64 + 255) / 256, 256, 0, s1>>>(part, Vb, nullptr, MN64, Dd);
    kw_kernel<<<dim3(Bb * NH, Dd / 256), 256, 0, s1>>>(Khb, Wq, KWh);
    vwt_kernel<<<dim3(Bb * NH, Dd / 128), 128, 0, s1>>>(Vb, Wo, VWTh);
    cudaEventRecord(evKV, s1);

    // ---- s2: corr_W fp16 conversion (off the critical path) ----
    cudaStreamWaitEvent(s2, evFork, 0);
    w_to_h<<<(WN4 + 255) / 256, 256, 0, s2>>>(corr_W, Wh, WN4);
    cudaEventRecord(evW, s2);

    // ---- main stream: stage 1 (sheaf) ----
    gist_cs_kernel<<<(Bb * DH + 255) / 256, 256>>>(gist_theta, gist_mag, gist_weights,
                                                   gist_strength, gc, gs);
    sheaf_cs_kernel<<<(4 * DH + 255) / 256, 256>>>(sheaf_thetas, shc, shs);
    ln_kernel<<<BT, 256>>>(x, S0, ln_sheaf_w, ln_sheaf_b);
    sheaf_pre_kernel<<<BT, 256>>>(S0, S1h, shc, shs, alpha);
    cudaStreamWaitEvent(0, evW, 0);
    // out = x + pre + pre @ corr_W^T   (fp16 MMA, fp32 accum)
    gemm_mma<<<gemm_big, 256, GEMM_MMA_SMEM>>>(S1h, Wh, out, x, S1h, Dd, Dd, Dd, 0, 0);

    // ---- stage 2: gist rotation (also emits S0h = fp16(LN_gca(out))) ----
    gist_fused_kernel<<<BT, 256>>>(out, S0h, ln_gist_w, ln_gist_b, gr_ln_w, gr_ln_b,
                                   ln_gca_w, ln_gca_b, gc, gs);

    // ---- join, then attention tail ----
    cudaStreamWaitEvent(0, evKV, 0);
    gemm_mma<<<gemm_sc, 256, GEMM_MMA_SMEM>>>(S0h, KWh, scorep, nullptr, nullptr,
                                              HK, Dd, Dd / SKS,
                                              (size_t)HK * Dd, (size_t)BT * HK);
    softmax_kernel<<<BT / 16, 256>>>(scorep, Ph);
    gemm_mma<<<gemm_out, 256, GEMM_MMA_SMEM>>>(Ph, VWTh, out, out, nullptr,
                                               Dd, HK, HK,
                                               (size_t)Dd * HK, 0);
}

// round 13
// speedup vs baseline: 1.0604x; 1.0404x over previous
#include <cuda_runtime.h>
#include <cuda_fp16.h>
#include <math.h>
#include <stdint.h>

// Problem constants
#define Bb 4
#define Tt 2048
#define Dd 2048
#define DH 1024
#define KK 16
#define NH 16
#define HD 128
#define BT (Bb*Tt)          // 8192 rows
#define KPAD 1088
#define NSPLIT 8
#define HK 256              // NH*KK
#define SKS 4               // split-K for scores GEMM

// ---------------- scratch (device globals; no allocation) ----------------
__device__ __half g_S0h[(size_t)BT * Dd];       // sheaf LN output, later LN_gca output (fp16)
__device__ __half g_S1h[(size_t)BT * Dd];       // sheaf pre (fp16)
__device__ __half g_Wh[(size_t)Dd * Dd];        // corr_W (fp16)
__device__ float  g_repr[64 * Dd];
__device__ float  g_Kh[64 * Dd];
__device__ float  g_Vv[64 * Dd];
__device__ float  g_packin[64 * KPAD];
__device__ float  g_Wpad[Dd * KPAD];
__device__ float  g_part[NSPLIT * 64 * Dd];
__device__ __half g_KWh[(size_t)Bb * HK * Dd];  // [b][hk][i]
__device__ __half g_VWTh[(size_t)Bb * Dd * HK]; // [b][o][hk]
__device__ float  g_scorep[(size_t)SKS * BT * HK];
__device__ __half g_Ph[(size_t)BT * HK];
__device__ float  g_shc[4 * DH];
__device__ float  g_shs[4 * DH];
__device__ float  g_gc[Bb * DH];
__device__ float  g_gs[Bb * DH];

// ---------------- helpers ----------------
__device__ __forceinline__ uint32_t smem_u32(const void* p) {
    uint32_t a;
    asm("{ .reg .u64 t; cvta.to.shared.u64 t, %1; cvt.u32.u64 %0, t; }" : "=r"(a) : "l"(p));
    return a;
}
__device__ __forceinline__ void cp16(uint32_t dst, const void* src) {
    asm volatile("cp.async.cg.shared.global [%0], [%1], 16;" :: "r"(dst), "l"(src));
}
__device__ __forceinline__ void ldsm_x4(uint32_t& r0, uint32_t& r1, uint32_t& r2, uint32_t& r3,
                                        uint32_t addr) {
    asm volatile("ldmatrix.sync.aligned.m8n8.x4.b16 {%0,%1,%2,%3}, [%4];"
                 : "=r"(r0), "=r"(r1), "=r"(r2), "=r"(r3) : "r"(addr));
}
__device__ __forceinline__ void mma_f16_16n8k16(float& c0, float& c1, float& c2, float& c3,
                                                uint32_t a0, uint32_t a1, uint32_t a2, uint32_t a3,
                                                uint32_t b0, uint32_t b1) {
    asm volatile(
        "mma.sync.aligned.m16n8k16.row.col.f32.f16.f16.f32 "
        "{%0,%1,%2,%3}, {%4,%5,%6,%7}, {%8,%9}, {%0,%1,%2,%3};"
        : "+f"(c0), "+f"(c1), "+f"(c2), "+f"(c3)
        : "r"(a0), "r"(a1), "r"(a2), "r"(a3), "r"(b0), "r"(b1));
}

// ============== fp16 warp-MMA NT GEMM: C(+add1 fp32)(+add2 fp16) = A @ W^T ==============
// A: [M,Kstride] fp16 row-major, W: [N,Kstride] fp16 row-major (batched by bm>>11 via wbstride).
// blockIdx.z selects K-chunk (kofs = z*Kchunk halfs) and C slab (z*czstride).
// 128x128 tile, 8 warps 2x4 (warp 64x32), K-chunk 64 halfs (128B rows), 3-stage cp.async.
#define KC 64
#define HALF_STAGE 16384
#define STAGE_BYTES 32768
#define NSTAGE 3
#define GEMM_MMA_SMEM (NSTAGE * STAGE_BYTES)   // 98304

__global__ void __launch_bounds__(256, 2) gemm_mma(const __half* __restrict__ A,
                                                   const __half* __restrict__ W,
                                                   float* __restrict__ C,
                                                   const float* __restrict__ add1,
                                                   const __half* __restrict__ add2h,
                                                   int N, int Kstride, int Kchunk,
                                                   size_t wbstride, size_t czstride)
{
    extern __shared__ char dyn[];
    const int tid = threadIdx.x;
    const int bm = blockIdx.y * 128;
    const int bn = blockIdx.x * 128;
    const int kofs = blockIdx.z * Kchunk;
    const int nt = Kchunk / KC;

    const int lane = tid & 31, wid = tid >> 5;
    const int wm = wid & 1, wn = wid >> 1;
    const int gid = lane >> 2, tig = lane & 3;
    const int am0 = wm * 64;
    const int bn0 = wn * 32;

    const uint32_t tile0 = smem_u32(dyn);
    const __half* Abase = A + (size_t)bm * Kstride + kofs;
    const __half* Wbase = W + (size_t)(bm >> 11) * wbstride + (size_t)bn * Kstride + kofs;
    C += (size_t)blockIdx.z * czstride;

    const int lrow = lane & 7, lmat = lane >> 3;
    uint32_t aoff[4]; int arm[4];
#pragma unroll
    for (int mf = 0; mf < 4; mf++) {
        int r = am0 + mf * 16 + ((lmat & 1) << 3) + lrow;
        aoff[mf] = (uint32_t)(r * 128);
        arm[mf] = r & 7;
    }
    const int achunk_add = lmat >> 1;
    uint32_t boff[2]; int brm[2];
#pragma unroll
    for (int p = 0; p < 2; p++) {
        int r = bn0 + ((p * 2 + (lmat >> 1)) << 3) + lrow;
        boff[p] = (uint32_t)(r * 128);
        brm[p] = r & 7;
    }
    const int bchunk_add = lmat & 1;

    float acc[4][4][4];
#pragma unroll
    for (int i = 0; i < 4; i++)
#pragma unroll
        for (int j = 0; j < 4; j++)
#pragma unroll
            for (int r = 0; r < 4; r++) acc[i][j][r] = 0.f;

    auto load_stage = [&](int kt) {
        uint32_t base = tile0 + (kt % NSTAGE) * STAGE_BYTES;
#pragma unroll
        for (int i = 0; i < 4; i++) {
            int c = i * 256 + tid;               // 0..1023
            int row = c >> 3, ch = c & 7;
            uint32_t dof = (uint32_t)(row * 128 + ((ch ^ (row & 7)) << 4));
            cp16(base + dof,              Abase + (size_t)row * Kstride + kt * KC + ch * 8);
            cp16(base + HALF_STAGE + dof, Wbase + (size_t)row * Kstride + kt * KC + ch * 8);
        }
        asm volatile("cp.async.commit_group;" ::: "memory");
    };

    load_stage(0);
    if (nt > 1) load_stage(1);

    for (int kt = 0; kt < nt; kt++) {
        if (kt + 1 < nt) asm volatile("cp.async.wait_group 1;" ::: "memory");
        else             asm volatile("cp.async.wait_group 0;" ::: "memory");
        __syncthreads();
        if (kt + 2 < nt) load_stage(kt + 2);

        uint32_t As_u = tile0 + (kt % NSTAGE) * STAGE_BYTES;
        uint32_t Bs_u = As_u + HALF_STAGE;
#pragma unroll
        for (int ks = 0; ks < 4; ks++) {        // 4 x k16 per 64-half chunk
            uint32_t a[4][4], b[4][2];
#pragma unroll
            for (int mf = 0; mf < 4; mf++) {
                uint32_t addr = As_u + aoff[mf] +
                                (uint32_t)(((2 * ks + achunk_add) ^ arm[mf]) << 4);
                ldsm_x4(a[mf][0], a[mf][1], a[mf][2], a[mf][3], addr);
            }
#pragma unroll
            for (int p = 0; p < 2; p++) {
                uint32_t addr = Bs_u + boff[p] +
                                (uint32_t)(((2 * ks + bchunk_add) ^ brm[p]) << 4);
                ldsm_x4(b[2 * p][0], b[2 * p][1], b[2 * p + 1][0], b[2 * p + 1][1], addr);
            }
#pragma unroll
            for (int mf = 0; mf < 4; mf++)
#pragma unroll
                for (int nf = 0; nf < 4; nf++)
                    mma_f16_16n8k16(acc[mf][nf][0], acc[mf][nf][1],
                                    acc[mf][nf][2], acc[mf][nf][3],
                                    a[mf][0], a[mf][1], a[mf][2], a[mf][3],
                                    b[nf][0], b[nf][1]);
        }
    }

#pragma unroll
    for (int mf = 0; mf < 4; mf++) {
        int row0 = bm + am0 + mf * 16 + gid;
        size_t ro0 = (size_t)row0 * N;
        size_t ro1 = ro0 + (size_t)8 * N;
#pragma unroll
        for (int nf = 0; nf < 4; nf++) {
            int col = bn + bn0 + nf * 8 + tig * 2;
            float2 v0 = make_float2(acc[mf][nf][0], acc[mf][nf][1]);
            float2 v1 = make_float2(acc[mf][nf][2], acc[mf][nf][3]);
            if (add1) {
                float2 t0 = *(const float2*)(add1 + ro0 + col);
                float2 t1 = *(const float2*)(add1 + ro1 + col);
                v0.x += t0.x; v0.y += t0.y; v1.x += t1.x; v1.y += t1.y;
            }
            if (add2h) {
                float2 t0 = __half22float2(*(const __half2*)(add2h + ro0 + col));
                float2 t1 = __half22float2(*(const __half2*)(add2h + ro1 + col));
                v0.x += t0.x; v0.y += t0.y; v1.x += t1.x; v1.y += t1.y;
            }
            *(float2*)(C + ro0 + col) = v0;
            *(float2*)(C + ro1 + col) = v1;
        }
    }
}

// ---------------- convert a weight matrix to fp16 ----------------
__global__ void w_to_h(const float* __restrict__ in, __half* __restrict__ out, int n4)
{
    int i = blockIdx.x * blockDim.x + threadIdx.x;
    if (i >= n4) return;
    float4 v = ((const float4*)in)[i];
    ((__half2*)out)[i * 2]     = __floats2half2_rn(v.x, v.y);
    ((__half2*)out)[i * 2 + 1] = __floats2half2_rn(v.z, v.w);
}

// ---------------- block reduction (sum of two values) ----------------
__device__ __forceinline__ void block_reduce2(float& a, float& b, float* sh)
{
    __syncthreads();
#pragma unroll
    for (int o = 16; o > 0; o >>= 1) {
        a += __shfl_xor_sync(0xffffffffu, a, o);
        b += __shfl_xor_sync(0xffffffffu, b, o);
    }
    int warp = threadIdx.x >> 5, lane = threadIdx.x & 31;
    if (lane == 0) { sh[warp] = a; sh[8 + warp] = b; }
    __syncthreads();
    if (threadIdx.x < 32) {
        float aa = (lane < 8) ? sh[lane] : 0.f;
        float bb = (lane < 8) ? sh[8 + lane] : 0.f;
#pragma unroll
        for (int o = 4; o > 0; o >>= 1) {
            aa += __shfl_xor_sync(0xffffffffu, aa, o);
            bb += __shfl_xor_sync(0xffffffffu, bb, o);
        }
        if (lane == 0) { sh[16] = aa; sh[17] = bb; }
    }
    __syncthreads();
    a = sh[16]; b = sh[17];
}

__device__ __forceinline__ float hsum4(float4 v) { return v.x + v.y + v.z + v.w; }
__device__ __forceinline__ float hsq4(float4 v)  { return v.x*v.x + v.y*v.y + v.z*v.z + v.w*v.w; }
__device__ __forceinline__ float4 h4_to_f4(__half2 a, __half2 b) {
    float2 fa = __half22float2(a), fb = __half22float2(b);
    return make_float4(fa.x, fa.y, fb.x, fb.y);
}

// ---------------- LayerNorm (fp16 out; sheaf path) ----------------
__global__ void __launch_bounds__(256) ln_kernel_h(const float* __restrict__ x,
                                                   __half* __restrict__ y,
                                                   const float* __restrict__ w,
                                                   const float* __restrict__ b)
{
    __shared__ float sh[32];
    size_t row = blockIdx.x;
    const float4* xr = (const float4*)(x + row * Dd);
    int tid = threadIdx.x;
    float4 v0 = xr[tid], v1 = xr[tid + 256];
    float s = hsum4(v0) + hsum4(v1);
    float s2 = hsq4(v0) + hsq4(v1);
    block_reduce2(s, s2, sh);
    float mu = s * (1.f / Dd);
    float inv = rsqrtf(s2 * (1.f / Dd) - mu * mu + 1e-5f);
    float4 w0 = ((const float4*)w)[tid], w1 = ((const float4*)w)[tid + 256];
    float4 b0 = ((const float4*)b)[tid], b1 = ((const float4*)b)[tid + 256];
    __half2* yr = (__half2*)(y + row * Dd);
    yr[tid * 2]           = __floats2half2_rn((v0.x - mu) * inv * w0.x + b0.x,
                                              (v0.y - mu) * inv * w0.y + b0.y);
    yr[tid * 2 + 1]       = __floats2half2_rn((v0.z - mu) * inv * w0.z + b0.z,
                                              (v0.w - mu) * inv * w0.w + b0.w);
    yr[512 + tid * 2]     = __floats2half2_rn((v1.x - mu) * inv * w1.x + b1.x,
                                              (v1.y - mu) * inv * w1.y + b1.y);
    yr[512 + tid * 2 + 1] = __floats2half2_rn((v1.z - mu) * inv * w1.z + b1.z,
                                              (v1.w - mu) * inv * w1.w + b1.w);
}

// ---------------- cos/sin of sheaf thetas ----------------
__global__ void sheaf_cs_kernel(const float* __restrict__ th,
                                float* __restrict__ c, float* __restrict__ s)
{
    int i = blockIdx.x * blockDim.x + threadIdx.x;
    if (i < 4 * DH) { float t = th[i]; c[i] = cosf(t); s[i] = sinf(t); }
}

// ---------------- sheaf: pre = xln - |alpha| * lap (fp16 in, fp16 out) ----------------
__global__ void __launch_bounds__(256) sheaf_pre_kernel(const __half* __restrict__ xlnh,
                                                        __half* __restrict__ preh,
                                                        const float* __restrict__ cs,
                                                        const float* __restrict__ sn,
                                                        const float* __restrict__ alpha_p)
{
    int row = blockIdx.x;
    int b = row / Tt, t = row % Tt;
    float a = fabsf(alpha_p[0]);
    const __half2* xr = (const __half2*)(xlnh + (size_t)row * Dd);
    int j = threadIdx.x;
    float4 xre = h4_to_f4(xr[j * 2], xr[j * 2 + 1]);
    float4 xim = h4_to_f4(xr[512 + j * 2], xr[512 + j * 2 + 1]);
    float4 lr = make_float4(4.f * xre.x, 4.f * xre.y, 4.f * xre.z, 4.f * xre.w);
    float4 li = make_float4(4.f * xim.x, 4.f * xim.y, 4.f * xim.z, 4.f * xim.w);
#pragma unroll
    for (int idx = 0; idx < 4; idx++) {
        int tn = t + (idx - 3);
        float4 yr = make_float4(0.f, 0.f, 0.f, 0.f), yi = yr;
        if (tn >= 0) {
            const __half2* y = (const __half2*)(xlnh + ((size_t)b * Tt + tn) * Dd);
            yr = h4_to_f4(y[j * 2], y[j * 2 + 1]);
            yi = h4_to_f4(y[512 + j * 2], y[512 + j * 2 + 1]);
        }
        float4 c = ((const float4*)cs)[idx * 256 + j];
        float4 ss = ((const float4*)sn)[idx * 256 + j];
        lr.x -= yr.x * c.x + yi.x * ss.x;  li.x -= yi.x * c.x - yr.x * ss.x;
        lr.y -= yr.y * c.y + yi.y * ss.y;  li.y -= yi.y * c.y - yr.y * ss.y;
        lr.z -= yr.z * c.z + yi.z * ss.z;  li.z -= yi.z * c.z - yr.z * ss.z;
        lr.w -= yr.w * c.w + yi.w * ss.w;  li.w -= yi.w * c.w - yr.w * ss.w;
    }
    __half2* pr = (__half2*)(preh + (size_t)row * Dd);
    pr[j * 2]           = __floats2half2_rn(xre.x - a * lr.x, xre.y - a * lr.y);
    pr[j * 2 + 1]       = __floats2half2_rn(xre.z - a * lr.z, xre.w - a * lr.w);
    pr[512 + j * 2]     = __floats2half2_rn(xim.x - a * li.x, xim.y - a * li.y);
    pr[512 + j * 2 + 1] = __floats2half2_rn(xim.z - a * li.z, xim.w - a * li.w);
}

// ---------------- gist angle cos/sin per (batch, dh) ----------------
__global__ void gist_cs_kernel(const float* __restrict__ gt,
                               const float* __restrict__ gm,
                               const float* __restrict__ gw,
                               const float* __restrict__ strength,
                               float* __restrict__ c, float* __restrict__ s)
{
    int i = blockIdx.x * blockDim.x + threadIdx.x;
    if (i >= Bb * DH) return;
    int b = i / DH, j = i % DH;
    float sig = 1.f / (1.f + expf(-strength[0]));
    float wsum = 0.f, th = 0.f;
#pragma unroll
    for (int k = 0; k < KK; k++) {
        float w = gw[b * KK + k] * gm[b * KK + k];
        wsum += w;
        th += w * gt[(size_t)(b * KK + k) * DH + j];
    }
    th = th / (wsum + 1e-8f) * sig;
    c[i] = cosf(th); s[i] = sinf(th);
}

// ---- fused: xn=LN(x); rot=rotate(xn); x += LN(rot)-xn; y = fp16(LN_gca(x_new)) ----
__global__ void __launch_bounds__(256) gist_fused_kernel(float* __restrict__ x,
    __half* __restrict__ y,
    const float* __restrict__ lnw, const float* __restrict__ lnb,
    const float* __restrict__ grw, const float* __restrict__ grb,
    const float* __restrict__ gcw, const float* __restrict__ gcb,
    const float* __restrict__ gc, const float* __restrict__ gs)
{
    __shared__ float sh[32];
    size_t row = blockIdx.x;
    int b = blockIdx.x / Tt;
    int tid = threadIdx.x;
    float4* xr = (float4*)(x + row * Dd);
    float4 v0 = xr[tid], v1 = xr[tid + 256];
    float s = hsum4(v0) + hsum4(v1);
    float s2 = hsq4(v0) + hsq4(v1);
    block_reduce2(s, s2, sh);
    float mu = s * (1.f / Dd);
    float inv = rsqrtf(s2 * (1.f / Dd) - mu * mu + 1e-5f);
    float4 w0 = ((const float4*)lnw)[tid], w1 = ((const float4*)lnw)[tid + 256];
    float4 bb0 = ((const float4*)lnb)[tid], bb1 = ((const float4*)lnb)[tid + 256];
    float4 xn0 = make_float4((v0.x - mu) * inv * w0.x + bb0.x, (v0.y - mu) * inv * w0.y + bb0.y,
                             (v0.z - mu) * inv * w0.z + bb0.z, (v0.w - mu) * inv * w0.w + bb0.w);
    float4 xn1 = make_float4((v1.x - mu) * inv * w1.x + bb1.x, (v1.y - mu) * inv * w1.y + bb1.y,
                             (v1.z - mu) * inv * w1.z + bb1.z, (v1.w - mu) * inv * w1.w + bb1.w);
    float4 c = ((const float4*)gc)[b * 256 + tid];
    float4 sn = ((const float4*)gs)[b * 256 + tid];
    float4 r0 = make_float4(xn0.x * c.x - xn1.x * sn.x, xn0.y * c.y - xn1.y * sn.y,
                            xn0.z * c.z - xn1.z * sn.z, xn0.w * c.w - xn1.w * sn.w);
    float4 r1 = make_float4(xn0.x * sn.x + xn1.x * c.x, xn0.y * sn.y + xn1.y * c.y,
                            xn0.z * sn.z + xn1.z * c.z, xn0.w * sn.w + xn1.w * c.w);
    float rs = hsum4(r0) + hsum4(r1);
    float rs2 = hsq4(r0) + hsq4(r1);
    block_reduce2(rs, rs2, sh);
    float mu2 = rs * (1.f / Dd);
    float inv2 = rsqrtf(rs2 * (1.f / Dd) - mu2 * mu2 + 1e-5f);
    float4 g0 = ((const float4*)grw)[tid], g1 = ((const float4*)grw)[tid + 256];
    float4 gb0 = ((const float4*)grb)[tid], gb1 = ((const float4*)grb)[tid + 256];
    float4 f0 = make_float4(v0.x + ((r0.x - mu2) * inv2 * g0.x + gb0.x) - xn0.x,
                            v0.y + ((r0.y - mu2) * inv2 * g0.y + gb0.y) - xn0.y,
                            v0.z + ((r0.z - mu2) * inv2 * g0.z + gb0.z) - xn0.z,
                            v0.w + ((r0.w - mu2) * inv2 * g0.w + gb0.w) - xn0.w);
    float4 f1 = make_float4(v1.x + ((r1.x - mu2) * inv2 * g1.x + gb1.x) - xn1.x,
                            v1.y + ((r1.y - mu2) * inv2 * g1.y + gb1.y) - xn1.y,
                            v1.z + ((r1.z - mu2) * inv2 * g1.z + gb1.z) - xn1.z,
                            v1.w + ((r1.w - mu2) * inv2 * g1.w + gb1.w) - xn1.w);
    float fs = hsum4(f0) + hsum4(f1);
    float fs2 = hsq4(f0) + hsq4(f1);
    block_reduce2(fs, fs2, sh);
    float mu3 = fs * (1.f / Dd);
    float inv3 = rsqrtf(fs2 * (1.f / Dd) - mu3 * mu3 + 1e-5f);
    float4 q0 = ((const float4*)gcw)[tid], q1 = ((const float4*)gcw)[tid + 256];
    float4 qb0 = ((const float4*)gcb)[tid], qb1 = ((const float4*)gcb)[tid + 256];
    xr[tid] = f0; xr[tid + 256] = f1;
    __half2* yr = (__half2*)(y + row * Dd);
    yr[tid * 2]           = __floats2half2_rn((f0.x - mu3) * inv3 * q0.x + qb0.x,
                                              (f0.y - mu3) * inv3 * q0.y + qb0.y);
    yr[tid * 2 + 1]       = __floats2half2_rn((f0.z - mu3) * inv3 * q0.z + qb0.z,
                                              (f0.w - mu3) * inv3 * q0.w + qb0.w);
    yr[512 + tid * 2]     = __floats2half2_rn((f1.x - mu3) * inv3 * q1.x + qb1.x,
                                              (f1.y - mu3) * inv3 * q1.y + qb1.y);
    yr[512 + tid * 2 + 1] = __floats2half2_rn((f1.z - mu3) * inv3 * q1.z + qb1.z,
                                              (f1.w - mu3) * inv3 * q1.w + qb1.w);
}

// ---------------- pack concat([gist_theta, gist_mag]) into [64, KPAD] ----------------
__global__ void pack_gist_in(const float* __restrict__ gt, const float* __restrict__ gm,
                             float* __restrict__ out)
{
    int i = blockIdx.x * blockDim.x + threadIdx.x;
    if (i >= 64 * KPAD) return;
    int r = i / KPAD, f = i % KPAD;
    float v = 0.f;
    if (f < DH) v = gt[(size_t)r * DH + f];
    else if (f == DH) v = gm[r];
    out[i] = v;
}

__global__ void pad_W_kernel(const float* __restrict__ W, float* __restrict__ out)
{
    int i = blockIdx.x * blockDim.x + threadIdx.x;
    if (i >= Dd * KPAD) return;
    int o = i / KPAD, f = i % KPAD;
    out[i] = (f < DH + 1) ? W[(size_t)o * (DH + 1) + f] : 0.f;
}

// ---------------- split-K SIMT GEMM for M=64 ----------------
__global__ void __launch_bounds__(256) splitk_nt(const float* __restrict__ A,
                                                 const float* __restrict__ W,
                                                 float* __restrict__ part,
                                                 int M, int N, int Ktot, int Kchunk)
{
    __shared__ float As[2][8][128];
    __shared__ float Bs[2][8][128];
    const int tid = threadIdx.x;
    const int bn = blockIdx.x * 128;
    const int kofs = blockIdx.y * Kchunk;
    const int lrow = tid >> 1;
    const int lcol = (tid & 1) << 2;
    const int tx = tid & 15;
    const int ty = tid >> 4;
    const int tm0 = ty * 8, tn0 = tx * 8;

    const float* Aptr = A + (size_t)lrow * Ktot + kofs + lcol;
    const float* Wptr = W + (size_t)(bn + lrow) * Ktot + kofs + lcol;
    const bool a_ok = lrow < M;

    float acc[8][8];
#pragma unroll
    for (int i = 0; i < 8; i++)
#pragma unroll
        for (int j = 0; j < 8; j++) acc[i][j] = 0.f;

    float4 pa = a_ok ? *(const float4*)Aptr : make_float4(0.f, 0.f, 0.f, 0.f);
    float4 pb = *(const float4*)Wptr;
    As[0][lcol + 0][lrow] = pa.x; As[0][lcol + 1][lrow] = pa.y;
    As[0][lcol + 2][lrow] = pa.z; As[0][lcol + 3][lrow] = pa.w;
    Bs[0][lcol + 0][lrow] = pb.x; Bs[0][lcol + 1][lrow] = pb.y;
    Bs[0][lcol + 2][lrow] = pb.z; Bs[0][lcol + 3][lrow] = pb.w;
    __syncthreads();

    const int ntiles = Kchunk >> 3;
    for (int kt = 0; kt < ntiles; kt++) {
        int buf = kt & 1;
        if (kt + 1 < ntiles) {
            pa = a_ok ? *(const float4*)(Aptr + (size_t)(kt + 1) * 8)
                      : make_float4(0.f, 0.f, 0.f, 0.f);
            pb = *(const float4*)(Wptr + (size_t)(kt + 1) * 8);
        }
#pragma unroll
        for (int k = 0; k < 8; k++) {
            float4 a0 = *(const float4*)&As[buf][k][tm0];
            float4 a1 = *(const float4*)&As[buf][k][tm0 + 4];
            float4 b0 = *(const float4*)&Bs[buf][k][tn0];
            float4 b1 = *(const float4*)&Bs[buf][k][tn0 + 4];
            float af[8] = {a0.x, a0.y, a0.z, a0.w, a1.x, a1.y, a1.z, a1.w};
            float bf[8] = {b0.x, b0.y, b0.z, b0.w, b1.x, b1.y, b1.z, b1.w};
#pragma unroll
            for (int i = 0; i < 8; i++)
#pragma unroll
                for (int j = 0; j < 8; j++)
                    acc[i][j] += af[i] * bf[j];
        }
        if (kt + 1 < ntiles) {
            int nb = buf ^ 1;
            As[nb][lcol + 0][lrow] = pa.x; As[nb][lcol + 1][lrow] = pa.y;
            As[nb][lcol + 2][lrow] = pa.z; As[nb][lcol + 3][lrow] = pa.w;
            Bs[nb][lcol + 0][lrow] = pb.x; Bs[nb][lcol + 1][lrow] = pb.y;
            Bs[nb][lcol + 2][lrow] = pb.z; Bs[nb][lcol + 3][lrow] = pb.w;
            __syncthreads();
        }
    }

    float* po = part + (size_t)blockIdx.y * M * N;
#pragma unroll
    for (int i = 0; i < 8; i++) {
        int gm = tm0 + i;
        if (gm < M) {
#pragma unroll
            for (int j = 0; j < 8; j += 4) {
                int gn = bn + tn0 + j;
                float4 v = make_float4(acc[i][j], acc[i][j + 1], acc[i][j + 2], acc[i][j + 3]);
                *(float4*)(po + (size_t)gm * N + gn) = v;
            }
        }
    }
}

// ---------------- reduce split-K partials (+optional bias) ----------------
__global__ void reduce_part(const float* __restrict__ part, float* __restrict__ C,
                            const float* __restrict__ bias, int MN, int N)
{
    int i = blockIdx.x * blockDim.x + threadIdx.x;
    if (i >= MN) return;
    float s = bias ? bias[i % N] : 0.f;
#pragma unroll
    for (int sp = 0; sp < NSPLIT; sp++) s += part[(size_t)sp * MN + i];
    C[i] = s;
}

// -------- KW[b][h*16+k][i] = fp16( (1/sqrt(128)) * sum_d Kh[b*16+k][h*128+d] * Wq[h*128+d][i] ) --------
__global__ void __launch_bounds__(256) kw_kernel(const float* __restrict__ Kh,
                                                 const float* __restrict__ Wq,
                                                 __half* __restrict__ KW)
{
    __shared__ float Khs[KK][HD];
    const int b = blockIdx.x >> 4, h = blockIdx.x & 15;
    const int tid = threadIdx.x;
    const int i = blockIdx.y * 256 + tid;
#pragma unroll
    for (int j = 0; j < 8; j++) {
        int e = tid + j * 256;
        int k = e >> 7, d = e & 127;
        Khs[k][d] = Kh[(size_t)(b * KK + k) * Dd + h * HD + d];
    }
    __syncthreads();
    float acc[KK];
#pragma unroll
    for (int k = 0; k < KK; k++) acc[k] = 0.f;
    const float* wcol = Wq + (size_t)(h * HD) * Dd + i;
    for (int d = 0; d < HD; d++) {
        float w = wcol[(size_t)d * Dd];
#pragma unroll
        for (int k = 0; k < KK; k++) acc[k] += Khs[k][d] * w;
    }
    __half* out = KW + (size_t)b * HK * Dd + (size_t)(h * KK) * Dd + i;
#pragma unroll
    for (int k = 0; k < KK; k++)
        out[(size_t)k * Dd] = __float2half_rn(acc[k] * 0.088388347648318447f);
}

// -------- VWT[b][o][h*16+k] = fp16( sum_d V[b*16+k][h*128+d] * Wo[o][h*128+d] ) --------
__global__ void __launch_bounds__(128) vwt_kernel(const float* __restrict__ V,
                                                  const float* __restrict__ Wo,
                                                  __half* __restrict__ VWT)
{
    __shared__ float Vs[KK][HD];
    const int b = blockIdx.x >> 4, h = blockIdx.x & 15;
    const int tid = threadIdx.x;
    const int o = blockIdx.y * 128 + tid;
#pragma unroll
    for (int j = 0; j < 16; j++) {
        int e = tid + j * 128;
        int k = e >> 7, d = e & 127;
        Vs[k][d] = V[(size_t)(b * KK + k) * Dd + h * HD + d];
    }
    __syncthreads();
    float acc[KK];
#pragma unroll
    for (int k = 0; k < KK; k++) acc[k] = 0.f;
    const float* wrow = Wo + (size_t)o * Dd + h * HD;
#pragma unroll 8
    for (int d4 = 0; d4 < HD / 4; d4++) {
        float4 w = *(const float4*)(wrow + d4 * 4);
#pragma unroll
        for (int k = 0; k < KK; k++) {
            acc[k] += Vs[k][d4 * 4 + 0] * w.x + Vs[k][d4 * 4 + 1] * w.y
                    + Vs[k][d4 * 4 + 2] * w.z + Vs[k][d4 * 4 + 3] * w.w;
        }
    }
    __half2* out = (__half2*)(VWT + (size_t)b * Dd * HK + (size_t)o * HK + h * KK);
#pragma unroll
    for (int k = 0; k < KK / 2; k++)
        out[k] = __floats2half2_rn(acc[2 * k], acc[2 * k + 1]);
}

// -------- softmax over 16 keys per head, fusing split-K score reduce; P in fp16 --------
__global__ void __launch_bounds__(256) softmax_kernel(const float* __restrict__ scorep,
                                                      __half* __restrict__ P)
{
    const int tid = threadIdx.x;
    const size_t row = blockIdx.x * 16 + (tid >> 4);
    const int h = tid & 15;
    float s[KK];
#pragma unroll
    for (int k = 0; k < KK; k++) {
        size_t idx = row * HK + h * KK + k;
        float v = scorep[idx];
#pragma unroll
        for (int sp = 1; sp < SKS; sp++) v += scorep[(size_t)sp * BT * HK + idx];
        s[k] = v;
    }
    float m = s[0];
#pragma unroll
    for (int k = 1; k < KK; k++) m = fmaxf(m, s[k]);
    float sum = 0.f;
#pragma unroll
    for (int k = 0; k < KK; k++) { s[k] = expf(s[k] - m); sum += s[k]; }
    float rinv = 1.f / sum;
#pragma unroll
    for (int k = 0; k < KK; k++)
        P[row * HK + h * KK + k] = __float2half_rn(s[k] * rinv);
}

// ---------------- orchestration ----------------
extern "C" void kernel_launch(void* const* d_in, const int* in_sizes, int n_in,
                              void* d_out, int out_size)
{
    const float* x            = (const float*)d_in[0];
    const float* gist_theta   = (const float*)d_in[1];
    const float* gist_mag     = (const float*)d_in[2];
    const float* gist_weights = (const float*)d_in[3];
    const float* ln_sheaf_w   = (const float*)d_in[4];
    const float* ln_sheaf_b   = (const float*)d_in[5];
    const float* sheaf_thetas = (const float*)d_in[6];
    const float* alpha        = (const float*)d_in[7];
    const float* corr_W       = (const float*)d_in[8];
    const float* ln_gist_w    = (const float*)d_in[9];
    const float* ln_gist_b    = (const float*)d_in[10];
    const float* gist_strength= (const float*)d_in[11];
    const float* gr_ln_w      = (const float*)d_in[12];
    const float* gr_ln_b      = (const float*)d_in[13];
    const float* ln_gca_w     = (const float*)d_in[14];
    const float* ln_gca_b     = (const float*)d_in[15];
    const float* Wq           = (const float*)d_in[16];
    const float* Wk           = (const float*)d_in[17];
    const float* Wv           = (const float*)d_in[18];
    const float* Wo           = (const float*)d_in[19];
    const float* gist_up_W    = (const float*)d_in[20];
    const float* gist_up_b    = (const float*)d_in[21];
    float* out = (float*)d_out;

    float *repr, *Khb, *Vb, *packin, *Wpad, *part, *scorep, *shc, *shs, *gc, *gs;
    __half *S0h, *S1h, *Wh, *KWh, *VWTh, *Ph;
    cudaGetSymbolAddress((void**)&S0h, g_S0h);
    cudaGetSymbolAddress((void**)&S1h, g_S1h);
    cudaGetSymbolAddress((void**)&Wh, g_Wh);
    cudaGetSymbolAddress((void**)&repr, g_repr);
    cudaGetSymbolAddress((void**)&Khb, g_Kh);
    cudaGetSymbolAddress((void**)&Vb, g_Vv);
    cudaGetSymbolAddress((void**)&packin, g_packin);
    cudaGetSymbolAddress((void**)&Wpad, g_Wpad);
    cudaGetSymbolAddress((void**)&part, g_part);
    cudaGetSymbolAddress((void**)&KWh, g_KWh);
    cudaGetSymbolAddress((void**)&VWTh, g_VWTh);
    cudaGetSymbolAddress((void**)&scorep, g_scorep);
    cudaGetSymbolAddress((void**)&Ph, g_Ph);
    cudaGetSymbolAddress((void**)&shc, g_shc);
    cudaGetSymbolAddress((void**)&shs, g_shs);
    cudaGetSymbolAddress((void**)&gc, g_gc);
    cudaGetSymbolAddress((void**)&gs, g_gs);

    // one-time setup (outside capture: first call is the correctness run)
    static cudaStream_t s1 = nullptr;
    static cudaEvent_t evFork = nullptr, evKV = nullptr;
    if (!s1) {
        cudaStreamCreateWithFlags(&s1, cudaStreamNonBlocking);
        cudaEventCreateWithFlags(&evFork, cudaEventDisableTiming);
        cudaEventCreateWithFlags(&evKV, cudaEventDisableTiming);
        cudaFuncSetAttribute(gemm_mma, cudaFuncAttributeMaxDynamicSharedMemorySize,
                             GEMM_MMA_SMEM);
    }

    dim3 gemm_big(Dd / 128, BT / 128, 1);    // (16, 64)
    dim3 gemm_sc(HK / 128, BT / 128, SKS);   // (2, 64, 4)
    dim3 gemm_out(Dd / 128, BT / 128, 1);    // (16, 64)
    dim3 sk_grid(Dd / 128, NSPLIT);          // (16, 8)
    const int WN4 = Dd * Dd / 4;
    const int MN64 = 64 * Dd;

    cudaEventRecord(evFork, 0);

    // ---- s1: KV-prep chain (independent of the x path) ----
    cudaStreamWaitEvent(s1, evFork, 0);
    pack_gist_in<<<(64 * KPAD + 255) / 256, 256, 0, s1>>>(gist_theta, gist_mag, packin);
    pad_W_kernel<<<(Dd * KPAD + 255) / 256, 256, 0, s1>>>(gist_up_W, Wpad);
    splitk_nt<<<sk_grid, 256, 0, s1>>>(packin, Wpad, part, 64, Dd, KPAD, KPAD / NSPLIT);
    reduce_part<<<(MN64 + 255) / 256, 256, 0, s1>>>(part, repr, gist_up_b, MN64, Dd);
    splitk_nt<<<sk_grid, 256, 0, s1>>>(repr, Wk, part, 64, Dd, Dd, Dd / NSPLIT);
    reduce_part<<<(MN64 + 255) / 256, 256, 0, s1>>>(part, Khb, nullptr, MN64, Dd);
    splitk_nt<<<sk_grid, 256, 0, s1>>>(repr, Wv, part, 64, Dd, Dd, Dd / NSPLIT);
    reduce_part<<<(MN64 + 255) / 256, 256, 0, s1>>>(part, Vb, nullptr, MN64, Dd);
    kw_kernel<<<dim3(Bb * NH, Dd / 256), 256, 0, s1>>>(Khb, Wq, KWh);
    vwt_kernel<<<dim3(Bb * NH, Dd / 128), 128, 0, s1>>>(Vb, Wo, VWTh);
    cudaEventRecord(evKV, s1);

    // ---- main stream: stage 1 (sheaf) ----
    w_to_h<<<(WN4 + 255) / 256, 256>>>(corr_W, Wh, WN4);
    gist_cs_kernel<<<(Bb * DH + 255) / 256, 256>>>(gist_theta, gist_mag, gist_weights,
                                                   gist_strength, gc, gs);
    sheaf_cs_kernel<<<(4 * DH + 255) / 256, 256>>>(sheaf_thetas, shc, shs);
    ln_kernel_h<<<BT, 256>>>(x, S0h, ln_sheaf_w, ln_sheaf_b);
    sheaf_pre_kernel<<<BT, 256>>>(S0h, S1h, shc, shs, alpha);
    // out = x + pre + pre @ corr_W^T   (fp16 MMA, fp32 accum)
    gemm_mma<<<gemm_big, 256, GEMM_MMA_SMEM>>>(S1h, Wh, out, x, S1h, Dd, Dd, Dd, 0, 0);

    // ---- stage 2: gist rotation (also emits S0h = fp16(LN_gca(out))) ----
    gist_fused_kernel<<<BT, 256>>>(out, S0h, ln_gist_w, ln_gist_b, gr_ln_w, gr_ln_b,
                                   ln_gca_w, ln_gca_b, gc, gs);

    // ---- join, then attention tail ----
    cudaStreamWaitEvent(0, evKV, 0);
    gemm_mma<<<gemm_sc, 256, GEMM_MMA_SMEM>>>(S0h, KWh, scorep, nullptr, nullptr,
                                              HK, Dd, Dd / SKS,
                                              (size_t)HK * Dd, (size_t)BT * HK);
    softmax_kernel<<<BT / 16, 256>>>(scorep, Ph);
    gemm_mma<<<gemm_out, 256, GEMM_MMA_SMEM>>>(Ph, VWTh, out, out, nullptr,
                                               Dd, HK, HK,
                                               (size_t)Dd * HK, 0);
}

// round 14
// speedup vs baseline: 1.0985x; 1.0360x over previous
#include <cuda_runtime.h>
#include <cuda_fp16.h>
#include <math.h>
#include <stdint.h>

// Problem constants
#define Bb 4
#define Tt 2048
#define Dd 2048
#define DH 1024
#define KK 16
#define NH 16
#define HD 128
#define BT (Bb*Tt)          // 8192 rows
#define KPAD 1088
#define NSPLIT 8
#define HK 256              // NH*KK
#define SKS 4               // split-K for scores GEMM

// ---------------- scratch (device globals; no allocation) ----------------
__device__ __half g_S0h[(size_t)BT * Dd];       // sheaf LN output, later LN_gca output (fp16)
__device__ __half g_S1h[(size_t)BT * Dd];       // sheaf pre (fp16)
__device__ __half g_Wh[(size_t)Dd * Dd];        // corr_W (fp16)
__device__ float  g_repr[64 * Dd];
__device__ float  g_Kh[64 * Dd];
__device__ float  g_Vv[64 * Dd];
__device__ float  g_packin[64 * KPAD];
__device__ float  g_Wpad[Dd * KPAD];
__device__ float  g_part[NSPLIT * 64 * Dd];
__device__ __half g_KWh[(size_t)Bb * HK * Dd];  // [b][hk][i]
__device__ __half g_VWTh[(size_t)Bb * Dd * HK]; // [b][o][hk]
__device__ float  g_scorep[(size_t)SKS * BT * HK];
__device__ __half g_Ph[(size_t)BT * HK];
__device__ float  g_shc[4 * DH];
__device__ float  g_shs[4 * DH];
__device__ float  g_gc[Bb * DH];
__device__ float  g_gs[Bb * DH];

// ---------------- helpers ----------------
__device__ __forceinline__ uint32_t smem_u32(const void* p) {
    uint32_t a;
    asm("{ .reg .u64 t; cvta.to.shared.u64 t, %1; cvt.u32.u64 %0, t; }" : "=r"(a) : "l"(p));
    return a;
}
__device__ __forceinline__ void cp16(uint32_t dst, const void* src) {
    asm volatile("cp.async.cg.shared.global [%0], [%1], 16;" :: "r"(dst), "l"(src));
}
__device__ __forceinline__ void ldsm_x4(uint32_t& r0, uint32_t& r1, uint32_t& r2, uint32_t& r3,
                                        uint32_t addr) {
    asm volatile("ldmatrix.sync.aligned.m8n8.x4.b16 {%0,%1,%2,%3}, [%4];"
                 : "=r"(r0), "=r"(r1), "=r"(r2), "=r"(r3) : "r"(addr));
}
__device__ __forceinline__ void mma_f16_16n8k16(float& c0, float& c1, float& c2, float& c3,
                                                uint32_t a0, uint32_t a1, uint32_t a2, uint32_t a3,
                                                uint32_t b0, uint32_t b1) {
    asm volatile(
        "mma.sync.aligned.m16n8k16.row.col.f32.f16.f16.f32 "
        "{%0,%1,%2,%3}, {%4,%5,%6,%7}, {%8,%9}, {%0,%1,%2,%3};"
        : "+f"(c0), "+f"(c1), "+f"(c2), "+f"(c3)
        : "r"(a0), "r"(a1), "r"(a2), "r"(a3), "r"(b0), "r"(b1));
}

// ============== fp16 warp-MMA NT GEMM: C(+add1 fp32)(+add2 fp16) = A @ W^T ==============
// A: [M,Kstride] fp16 row-major, W: [N,Kstride] fp16 row-major (batched by bm>>11 via wbstride).
// blockIdx.z selects K-chunk (kofs = z*Kchunk halfs) and C slab (z*czstride).
// 128x128 tile, 8 warps 2x4 (warp 64x32), K-chunk 64 halfs (128B rows), 3-stage cp.async.
#define KC 64
#define HALF_STAGE 16384
#define STAGE_BYTES 32768
#define NSTAGE 3
#define GEMM_MMA_SMEM (NSTAGE * STAGE_BYTES)   // 98304

__global__ void __launch_bounds__(256, 2) gemm_mma(const __half* __restrict__ A,
                                                   const __half* __restrict__ W,
                                                   float* __restrict__ C,
                                                   const float* __restrict__ add1,
                                                   const __half* __restrict__ add2h,
                                                   int N, int Kstride, int Kchunk,
                                                   size_t wbstride, size_t czstride)
{
    extern __shared__ char dyn[];
    const int tid = threadIdx.x;
    const int bm = blockIdx.y * 128;
    const int bn = blockIdx.x * 128;
    const int kofs = blockIdx.z * Kchunk;
    const int nt = Kchunk / KC;

    const int lane = tid & 31, wid = tid >> 5;
    const int wm = wid & 1, wn = wid >> 1;
    const int gid = lane >> 2, tig = lane & 3;
    const int am0 = wm * 64;
    const int bn0 = wn * 32;

    const uint32_t tile0 = smem_u32(dyn);
    const __half* Abase = A + (size_t)bm * Kstride + kofs;
    const __half* Wbase = W + (size_t)(bm >> 11) * wbstride + (size_t)bn * Kstride + kofs;
    C += (size_t)blockIdx.z * czstride;

    const int lrow = lane & 7, lmat = lane >> 3;
    uint32_t aoff[4]; int arm[4];
#pragma unroll
    for (int mf = 0; mf < 4; mf++) {
        int r = am0 + mf * 16 + ((lmat & 1) << 3) + lrow;
        aoff[mf] = (uint32_t)(r * 128);
        arm[mf] = r & 7;
    }
    const int achunk_add = lmat >> 1;
    uint32_t boff[2]; int brm[2];
#pragma unroll
    for (int p = 0; p < 2; p++) {
        int r = bn0 + ((p * 2 + (lmat >> 1)) << 3) + lrow;
        boff[p] = (uint32_t)(r * 128);
        brm[p] = r & 7;
    }
    const int bchunk_add = lmat & 1;

    float acc[4][4][4];
#pragma unroll
    for (int i = 0; i < 4; i++)
#pragma unroll
        for (int j = 0; j < 4; j++)
#pragma unroll
            for (int r = 0; r < 4; r++) acc[i][j][r] = 0.f;

    auto load_stage = [&](int kt) {
        uint32_t base = tile0 + (kt % NSTAGE) * STAGE_BYTES;
#pragma unroll
        for (int i = 0; i < 4; i++) {
            int c = i * 256 + tid;               // 0..1023
            int row = c >> 3, ch = c & 7;
            uint32_t dof = (uint32_t)(row * 128 + ((ch ^ (row & 7)) << 4));
            cp16(base + dof,              Abase + (size_t)row * Kstride + kt * KC + ch * 8);
            cp16(base + HALF_STAGE + dof, Wbase + (size_t)row * Kstride + kt * KC + ch * 8);
        }
        asm volatile("cp.async.commit_group;" ::: "memory");
    };

    load_stage(0);
    if (nt > 1) load_stage(1);

    for (int kt = 0; kt < nt; kt++) {
        if (kt + 1 < nt) asm volatile("cp.async.wait_group 1;" ::: "memory");
        else             asm volatile("cp.async.wait_group 0;" ::: "memory");
        __syncthreads();
        if (kt + 2 < nt) load_stage(kt + 2);

        uint32_t As_u = tile0 + (kt % NSTAGE) * STAGE_BYTES;
        uint32_t Bs_u = As_u + HALF_STAGE;
#pragma unroll
        for (int ks = 0; ks < 4; ks++) {        // 4 x k16 per 64-half chunk
            uint32_t a[4][4], b[4][2];
#pragma unroll
            for (int mf = 0; mf < 4; mf++) {
                uint32_t addr = As_u + aoff[mf] +
                                (uint32_t)(((2 * ks + achunk_add) ^ arm[mf]) << 4);
                ldsm_x4(a[mf][0], a[mf][1], a[mf][2], a[mf][3], addr);
            }
#pragma unroll
            for (int p = 0; p < 2; p++) {
                uint32_t addr = Bs_u + boff[p] +
                                (uint32_t)(((2 * ks + bchunk_add) ^ brm[p]) << 4);
                ldsm_x4(b[2 * p][0], b[2 * p][1], b[2 * p + 1][0], b[2 * p + 1][1], addr);
            }
#pragma unroll
            for (int mf = 0; mf < 4; mf++)
#pragma unroll
                for (int nf = 0; nf < 4; nf++)
                    mma_f16_16n8k16(acc[mf][nf][0], acc[mf][nf][1],
                                    acc[mf][nf][2], acc[mf][nf][3],
                                    a[mf][0], a[mf][1], a[mf][2], a[mf][3],
                                    b[nf][0], b[nf][1]);
        }
    }

#pragma unroll
    for (int mf = 0; mf < 4; mf++) {
        int row0 = bm + am0 + mf * 16 + gid;
        size_t ro0 = (size_t)row0 * N;
        size_t ro1 = ro0 + (size_t)8 * N;
#pragma unroll
        for (int nf = 0; nf < 4; nf++) {
            int col = bn + bn0 + nf * 8 + tig * 2;
            float2 v0 = make_float2(acc[mf][nf][0], acc[mf][nf][1]);
            float2 v1 = make_float2(acc[mf][nf][2], acc[mf][nf][3]);
            if (add1) {
                float2 t0 = *(const float2*)(add1 + ro0 + col);
                float2 t1 = *(const float2*)(add1 + ro1 + col);
                v0.x += t0.x; v0.y += t0.y; v1.x += t1.x; v1.y += t1.y;
            }
            if (add2h) {
                float2 t0 = __half22float2(*(const __half2*)(add2h + ro0 + col));
                float2 t1 = __half22float2(*(const __half2*)(add2h + ro1 + col));
                v0.x += t0.x; v0.y += t0.y; v1.x += t1.x; v1.y += t1.y;
            }
            *(float2*)(C + ro0 + col) = v0;
            *(float2*)(C + ro1 + col) = v1;
        }
    }
}

// ---------------- convert a weight matrix to fp16 ----------------
__global__ void w_to_h(const float* __restrict__ in, __half* __restrict__ out, int n4)
{
    int i = blockIdx.x * blockDim.x + threadIdx.x;
    if (i >= n4) return;
    float4 v = ((const float4*)in)[i];
    ((__half2*)out)[i * 2]     = __floats2half2_rn(v.x, v.y);
    ((__half2*)out)[i * 2 + 1] = __floats2half2_rn(v.z, v.w);
}

// ---------------- block reduction (sum of two values) ----------------
__device__ __forceinline__ void block_reduce2(float& a, float& b, float* sh)
{
    __syncthreads();
#pragma unroll
    for (int o = 16; o > 0; o >>= 1) {
        a += __shfl_xor_sync(0xffffffffu, a, o);
        b += __shfl_xor_sync(0xffffffffu, b, o);
    }
    int warp = threadIdx.x >> 5, lane = threadIdx.x & 31;
    if (lane == 0) { sh[warp] = a; sh[8 + warp] = b; }
    __syncthreads();
    if (threadIdx.x < 32) {
        float aa = (lane < 8) ? sh[lane] : 0.f;
        float bb = (lane < 8) ? sh[8 + lane] : 0.f;
#pragma unroll
        for (int o = 4; o > 0; o >>= 1) {
            aa += __shfl_xor_sync(0xffffffffu, aa, o);
            bb += __shfl_xor_sync(0xffffffffu, bb, o);
        }
        if (lane == 0) { sh[16] = aa; sh[17] = bb; }
    }
    __syncthreads();
    a = sh[16]; b = sh[17];
}

__device__ __forceinline__ float hsum4(float4 v) { return v.x + v.y + v.z + v.w; }
__device__ __forceinline__ float hsq4(float4 v)  { return v.x*v.x + v.y*v.y + v.z*v.z + v.w*v.w; }
__device__ __forceinline__ float4 h4_to_f4(__half2 a, __half2 b) {
    float2 fa = __half22float2(a), fb = __half22float2(b);
    return make_float4(fa.x, fa.y, fb.x, fb.y);
}

// ---------------- LayerNorm (fp16 out; sheaf path) ----------------
__global__ void __launch_bounds__(256) ln_kernel_h(const float* __restrict__ x,
                                                   __half* __restrict__ y,
                                                   const float* __restrict__ w,
                                                   const float* __restrict__ b)
{
    __shared__ float sh[32];
    size_t row = blockIdx.x;
    const float4* xr = (const float4*)(x + row * Dd);
    int tid = threadIdx.x;
    float4 v0 = xr[tid], v1 = xr[tid + 256];
    float s = hsum4(v0) + hsum4(v1);
    float s2 = hsq4(v0) + hsq4(v1);
    block_reduce2(s, s2, sh);
    float mu = s * (1.f / Dd);
    float inv = rsqrtf(s2 * (1.f / Dd) - mu * mu + 1e-5f);
    float4 w0 = ((const float4*)w)[tid], w1 = ((const float4*)w)[tid + 256];
    float4 b0 = ((const float4*)b)[tid], b1 = ((const float4*)b)[tid + 256];
    __half2* yr = (__half2*)(y + row * Dd);
    yr[tid * 2]           = __floats2half2_rn((v0.x - mu) * inv * w0.x + b0.x,
                                              (v0.y - mu) * inv * w0.y + b0.y);
    yr[tid * 2 + 1]       = __floats2half2_rn((v0.z - mu) * inv * w0.z + b0.z,
                                              (v0.w - mu) * inv * w0.w + b0.w);
    yr[512 + tid * 2]     = __floats2half2_rn((v1.x - mu) * inv * w1.x + b1.x,
                                              (v1.y - mu) * inv * w1.y + b1.y);
    yr[512 + tid * 2 + 1] = __floats2half2_rn((v1.z - mu) * inv * w1.z + b1.z,
                                              (v1.w - mu) * inv * w1.w + b1.w);
}

// ------ merged angles: sheaf cos/sin (4*DH) + gist cos/sin (Bb*DH) in one launch ------
__global__ void __launch_bounds__(256) angles_kernel(const float* __restrict__ th,
                                                     float* __restrict__ shc,
                                                     float* __restrict__ shs,
                                                     const float* __restrict__ gt,
                                                     const float* __restrict__ gm,
                                                     const float* __restrict__ gw,
                                                     const float* __restrict__ strength,
                                                     float* __restrict__ gc,
                                                     float* __restrict__ gs)
{
    int i = blockIdx.x * blockDim.x + threadIdx.x;
    if (i < 4 * DH) {
        float t = th[i];
        shc[i] = cosf(t); shs[i] = sinf(t);
        return;
    }
    int g = i - 4 * DH;
    if (g >= Bb * DH) return;
    int b = g / DH, j = g % DH;
    float sig = 1.f / (1.f + expf(-strength[0]));
    float wsum = 0.f, thv = 0.f;
#pragma unroll
    for (int k = 0; k < KK; k++) {
        float w = gw[b * KK + k] * gm[b * KK + k];
        wsum += w;
        thv += w * gt[(size_t)(b * KK + k) * DH + j];
    }
    thv = thv / (wsum + 1e-8f) * sig;
    gc[g] = cosf(thv); gs[g] = sinf(thv);
}

// ---------------- sheaf: pre = xln - |alpha| * lap (fp16 in, fp16 out) ----------------
__global__ void __launch_bounds__(256) sheaf_pre_kernel(const __half* __restrict__ xlnh,
                                                        __half* __restrict__ preh,
                                                        const float* __restrict__ cs,
                                                        const float* __restrict__ sn,
                                                        const float* __restrict__ alpha_p)
{
    int row = blockIdx.x;
    int b = row / Tt, t = row % Tt;
    float a = fabsf(alpha_p[0]);
    const __half2* xr = (const __half2*)(xlnh + (size_t)row * Dd);
    int j = threadIdx.x;
    float4 xre = h4_to_f4(xr[j * 2], xr[j * 2 + 1]);
    float4 xim = h4_to_f4(xr[512 + j * 2], xr[512 + j * 2 + 1]);
    float4 lr = make_float4(4.f * xre.x, 4.f * xre.y, 4.f * xre.z, 4.f * xre.w);
    float4 li = make_float4(4.f * xim.x, 4.f * xim.y, 4.f * xim.z, 4.f * xim.w);
#pragma unroll
    for (int idx = 0; idx < 4; idx++) {
        int tn = t + (idx - 3);
        float4 yr = make_float4(0.f, 0.f, 0.f, 0.f), yi = yr;
        if (tn >= 0) {
            const __half2* y = (const __half2*)(xlnh + ((size_t)b * Tt + tn) * Dd);
            yr = h4_to_f4(y[j * 2], y[j * 2 + 1]);
            yi = h4_to_f4(y[512 + j * 2], y[512 + j * 2 + 1]);
        }
        float4 c = ((const float4*)cs)[idx * 256 + j];
        float4 ss = ((const float4*)sn)[idx * 256 + j];
        lr.x -= yr.x * c.x + yi.x * ss.x;  li.x -= yi.x * c.x - yr.x * ss.x;
        lr.y -= yr.y * c.y + yi.y * ss.y;  li.y -= yi.y * c.y - yr.y * ss.y;
        lr.z -= yr.z * c.z + yi.z * ss.z;  li.z -= yi.z * c.z - yr.z * ss.z;
        lr.w -= yr.w * c.w + yi.w * ss.w;  li.w -= yi.w * c.w - yr.w * ss.w;
    }
    __half2* pr = (__half2*)(preh + (size_t)row * Dd);
    pr[j * 2]           = __floats2half2_rn(xre.x - a * lr.x, xre.y - a * lr.y);
    pr[j * 2 + 1]       = __floats2half2_rn(xre.z - a * lr.z, xre.w - a * lr.w);
    pr[512 + j * 2]     = __floats2half2_rn(xim.x - a * li.x, xim.y - a * li.y);
    pr[512 + j * 2 + 1] = __floats2half2_rn(xim.z - a * li.z, xim.w - a * li.w);
}

// ---- fused: xn=LN(x); rot=rotate(xn); x += LN(rot)-xn; y = fp16(LN_gca(x_new)) ----
__global__ void __launch_bounds__(256) gist_fused_kernel(float* __restrict__ x,
    __half* __restrict__ y,
    const float* __restrict__ lnw, const float* __restrict__ lnb,
    const float* __restrict__ grw, const float* __restrict__ grb,
    const float* __restrict__ gcw, const float* __restrict__ gcb,
    const float* __restrict__ gc, const float* __restrict__ gs)
{
    __shared__ float sh[32];
    size_t row = blockIdx.x;
    int b = blockIdx.x / Tt;
    int tid = threadIdx.x;
    float4* xr = (float4*)(x + row * Dd);
    float4 v0 = xr[tid], v1 = xr[tid + 256];
    float s = hsum4(v0) + hsum4(v1);
    float s2 = hsq4(v0) + hsq4(v1);
    block_reduce2(s, s2, sh);
    float mu = s * (1.f / Dd);
    float inv = rsqrtf(s2 * (1.f / Dd) - mu * mu + 1e-5f);
    float4 w0 = ((const float4*)lnw)[tid], w1 = ((const float4*)lnw)[tid + 256];
    float4 bb0 = ((const float4*)lnb)[tid], bb1 = ((const float4*)lnb)[tid + 256];
    float4 xn0 = make_float4((v0.x - mu) * inv * w0.x + bb0.x, (v0.y - mu) * inv * w0.y + bb0.y,
                             (v0.z - mu) * inv * w0.z + bb0.z, (v0.w - mu) * inv * w0.w + bb0.w);
    float4 xn1 = make_float4((v1.x - mu) * inv * w1.x + bb1.x, (v1.y - mu) * inv * w1.y + bb1.y,
                             (v1.z - mu) * inv * w1.z + bb1.z, (v1.w - mu) * inv * w1.w + bb1.w);
    float4 c = ((const float4*)gc)[b * 256 + tid];
    float4 sn = ((const float4*)gs)[b * 256 + tid];
    float4 r0 = make_float4(xn0.x * c.x - xn1.x * sn.x, xn0.y * c.y - xn1.y * sn.y,
                            xn0.z * c.z - xn1.z * sn.z, xn0.w * c.w - xn1.w * sn.w);
    float4 r1 = make_float4(xn0.x * sn.x + xn1.x * c.x, xn0.y * sn.y + xn1.y * c.y,
                            xn0.z * sn.z + xn1.z * c.z, xn0.w * sn.w + xn1.w * c.w);
    float rs = hsum4(r0) + hsum4(r1);
    float rs2 = hsq4(r0) + hsq4(r1);
    block_reduce2(rs, rs2, sh);
    float mu2 = rs * (1.f / Dd);
    float inv2 = rsqrtf(rs2 * (1.f / Dd) - mu2 * mu2 + 1e-5f);
    float4 g0 = ((const float4*)grw)[tid], g1 = ((const float4*)grw)[tid + 256];
    float4 gb0 = ((const float4*)grb)[tid], gb1 = ((const float4*)grb)[tid + 256];
    float4 f0 = make_float4(v0.x + ((r0.x - mu2) * inv2 * g0.x + gb0.x) - xn0.x,
                            v0.y + ((r0.y - mu2) * inv2 * g0.y + gb0.y) - xn0.y,
                            v0.z + ((r0.z - mu2) * inv2 * g0.z + gb0.z) - xn0.z,
                            v0.w + ((r0.w - mu2) * inv2 * g0.w + gb0.w) - xn0.w);
    float4 f1 = make_float4(v1.x + ((r1.x - mu2) * inv2 * g1.x + gb1.x) - xn1.x,
                            v1.y + ((r1.y - mu2) * inv2 * g1.y + gb1.y) - xn1.y,
                            v1.z + ((r1.z - mu2) * inv2 * g1.z + gb1.z) - xn1.z,
                            v1.w + ((r1.w - mu2) * inv2 * g1.w + gb1.w) - xn1.w);
    float fs = hsum4(f0) + hsum4(f1);
    float fs2 = hsq4(f0) + hsq4(f1);
    block_reduce2(fs, fs2, sh);
    float mu3 = fs * (1.f / Dd);
    float inv3 = rsqrtf(fs2 * (1.f / Dd) - mu3 * mu3 + 1e-5f);
    float4 q0 = ((const float4*)gcw)[tid], q1 = ((const float4*)gcw)[tid + 256];
    float4 qb0 = ((const float4*)gcb)[tid], qb1 = ((const float4*)gcb)[tid + 256];
    xr[tid] = f0; xr[tid + 256] = f1;
    __half2* yr = (__half2*)(y + row * Dd);
    yr[tid * 2]           = __floats2half2_rn((f0.x - mu3) * inv3 * q0.x + qb0.x,
                                              (f0.y - mu3) * inv3 * q0.y + qb0.y);
    yr[tid * 2 + 1]       = __floats2half2_rn((f0.z - mu3) * inv3 * q0.z + qb0.z,
                                              (f0.w - mu3) * inv3 * q0.w + qb0.w);
    yr[512 + tid * 2]     = __floats2half2_rn((f1.x - mu3) * inv3 * q1.x + qb1.x,
                                              (f1.y - mu3) * inv3 * q1.y + qb1.y);
    yr[512 + tid * 2 + 1] = __floats2half2_rn((f1.z - mu3) * inv3 * q1.z + qb1.z,
                                              (f1.w - mu3) * inv3 * q1.w + qb1.w);
}

// ---------------- pack concat([gist_theta, gist_mag]) into [64, KPAD] ----------------
__global__ void pack_gist_in(const float* __restrict__ gt, const float* __restrict__ gm,
                             float* __restrict__ out)
{
    int i = blockIdx.x * blockDim.x + threadIdx.x;
    if (i >= 64 * KPAD) return;
    int r = i / KPAD, f = i % KPAD;
    float v = 0.f;
    if (f < DH) v = gt[(size_t)r * DH + f];
    else if (f == DH) v = gm[r];
    out[i] = v;
}

__global__ void pad_W_kernel(const float* __restrict__ W, float* __restrict__ out)
{
    int i = blockIdx.x * blockDim.x + threadIdx.x;
    if (i >= Dd * KPAD) return;
    int o = i / KPAD, f = i % KPAD;
    out[i] = (f < DH + 1) ? W[(size_t)o * (DH + 1) + f] : 0.f;
}

// ---------------- split-K SIMT GEMM for M=64 ----------------
__global__ void __launch_bounds__(256) splitk_nt(const float* __restrict__ A,
                                                 const float* __restrict__ W,
                                                 float* __restrict__ part,
                                                 int M, int N, int Ktot, int Kchunk)
{
    __shared__ float As[2][8][128];
    __shared__ float Bs[2][8][128];
    const int tid = threadIdx.x;
    const int bn = blockIdx.x * 128;
    const int kofs = blockIdx.y * Kchunk;
    const int lrow = tid >> 1;
    const int lcol = (tid & 1) << 2;
    const int tx = tid & 15;
    const int ty = tid >> 4;
    const int tm0 = ty * 8, tn0 = tx * 8;

    const float* Aptr = A + (size_t)lrow * Ktot + kofs + lcol;
    const float* Wptr = W + (size_t)(bn + lrow) * Ktot + kofs + lcol;
    const bool a_ok = lrow < M;

    float acc[8][8];
#pragma unroll
    for (int i = 0; i < 8; i++)
#pragma unroll
        for (int j = 0; j < 8; j++) acc[i][j] = 0.f;

    float4 pa = a_ok ? *(const float4*)Aptr : make_float4(0.f, 0.f, 0.f, 0.f);
    float4 pb = *(const float4*)Wptr;
    As[0][lcol + 0][lrow] = pa.x; As[0][lcol + 1][lrow] = pa.y;
    As[0][lcol + 2][lrow] = pa.z; As[0][lcol + 3][lrow] = pa.w;
    Bs[0][lcol + 0][lrow] = pb.x; Bs[0][lcol + 1][lrow] = pb.y;
    Bs[0][lcol + 2][lrow] = pb.z; Bs[0][lcol + 3][lrow] = pb.w;
    __syncthreads();

    const int ntiles = Kchunk >> 3;
    for (int kt = 0; kt < ntiles; kt++) {
        int buf = kt & 1;
        if (kt + 1 < ntiles) {
            pa = a_ok ? *(const float4*)(Aptr + (size_t)(kt + 1) * 8)
                      : make_float4(0.f, 0.f, 0.f, 0.f);
            pb = *(const float4*)(Wptr + (size_t)(kt + 1) * 8);
        }
#pragma unroll
        for (int k = 0; k < 8; k++) {
            float4 a0 = *(const float4*)&As[buf][k][tm0];
            float4 a1 = *(const float4*)&As[buf][k][tm0 + 4];
            float4 b0 = *(const float4*)&Bs[buf][k][tn0];
            float4 b1 = *(const float4*)&Bs[buf][k][tn0 + 4];
            float af[8] = {a0.x, a0.y, a0.z, a0.w, a1.x, a1.y, a1.z, a1.w};
            float bf[8] = {b0.x, b0.y, b0.z, b0.w, b1.x, b1.y, b1.z, b1.w};
#pragma unroll
            for (int i = 0; i < 8; i++)
#pragma unroll
                for (int j = 0; j < 8; j++)
                    acc[i][j] += af[i] * bf[j];
        }
        if (kt + 1 < ntiles) {
            int nb = buf ^ 1;
            As[nb][lcol + 0][lrow] = pa.x; As[nb][lcol + 1][lrow] = pa.y;
            As[nb][lcol + 2][lrow] = pa.z; As[nb][lcol + 3][lrow] = pa.w;
            Bs[nb][lcol + 0][lrow] = pb.x; Bs[nb][lcol + 1][lrow] = pb.y;
            Bs[nb][lcol + 2][lrow] = pb.z; Bs[nb][lcol + 3][lrow] = pb.w;
            __syncthreads();
        }
    }

    float* po = part + (size_t)blockIdx.y * M * N;
#pragma unroll
    for (int i = 0; i < 8; i++) {
        int gm = tm0 + i;
        if (gm < M) {
#pragma unroll
            for (int j = 0; j < 8; j += 4) {
                int gn = bn + tn0 + j;
                float4 v = make_float4(acc[i][j], acc[i][j + 1], acc[i][j + 2], acc[i][j + 3]);
                *(float4*)(po + (size_t)gm * N + gn) = v;
            }
        }
    }
}

// ---------------- reduce split-K partials (+optional bias) ----------------
__global__ void reduce_part(const float* __restrict__ part, float* __restrict__ C,
                            const float* __restrict__ bias, int MN, int N)
{
    int i = blockIdx.x * blockDim.x + threadIdx.x;
    if (i >= MN) return;
    float s = bias ? bias[i % N] : 0.f;
#pragma unroll
    for (int sp = 0; sp < NSPLIT; sp++) s += part[(size_t)sp * MN + i];
    C[i] = s;
}

// -------- KW[b][h*16+k][i] = fp16( (1/sqrt(128)) * sum_d Kh[b*16+k][h*128+d] * Wq[h*128+d][i] ) --------
__global__ void __launch_bounds__(256) kw_kernel(const float* __restrict__ Kh,
                                                 const float* __restrict__ Wq,
                                                 __half* __restrict__ KW)
{
    __shared__ float Khs[KK][HD];
    const int b = blockIdx.x >> 4, h = blockIdx.x & 15;
    const int tid = threadIdx.x;
    const int i = blockIdx.y * 256 + tid;
#pragma unroll
    for (int j = 0; j < 8; j++) {
        int e = tid + j * 256;
        int k = e >> 7, d = e & 127;
        Khs[k][d] = Kh[(size_t)(b * KK + k) * Dd + h * HD + d];
    }
    __syncthreads();
    float acc[KK];
#pragma unroll
    for (int k = 0; k < KK; k++) acc[k] = 0.f;
    const float* wcol = Wq + (size_t)(h * HD) * Dd + i;
    for (int d = 0; d < HD; d++) {
        float w = wcol[(size_t)d * Dd];
#pragma unroll
        for (int k = 0; k < KK; k++) acc[k] += Khs[k][d] * w;
    }
    __half* out = KW + (size_t)b * HK * Dd + (size_t)(h * KK) * Dd + i;
#pragma unroll
    for (int k = 0; k < KK; k++)
        out[(size_t)k * Dd] = __float2half_rn(acc[k] * 0.088388347648318447f);
}

// -------- VWT[b][o][h*16+k] = fp16( sum_d V[b*16+k][h*128+d] * Wo[o][h*128+d] ) --------
__global__ void __launch_bounds__(128) vwt_kernel(const float* __restrict__ V,
                                                  const float* __restrict__ Wo,
                                                  __half* __restrict__ VWT)
{
    __shared__ float Vs[KK][HD];
    const int b = blockIdx.x >> 4, h = blockIdx.x & 15;
    const int tid = threadIdx.x;
    const int o = blockIdx.y * 128 + tid;
#pragma unroll
    for (int j = 0; j < 16; j++) {
        int e = tid + j * 128;
        int k = e >> 7, d = e & 127;
        Vs[k][d] = V[(size_t)(b * KK + k) * Dd + h * HD + d];
    }
    __syncthreads();
    float acc[KK];
#pragma unroll
    for (int k = 0; k < KK; k++) acc[k] = 0.f;
    const float* wrow = Wo + (size_t)o * Dd + h * HD;
#pragma unroll 8
    for (int d4 = 0; d4 < HD / 4; d4++) {
        float4 w = *(const float4*)(wrow + d4 * 4);
#pragma unroll
        for (int k = 0; k < KK; k++) {
            acc[k] += Vs[k][d4 * 4 + 0] * w.x + Vs[k][d4 * 4 + 1] * w.y
                    + Vs[k][d4 * 4 + 2] * w.z + Vs[k][d4 * 4 + 3] * w.w;
        }
    }
    __half2* out = (__half2*)(VWT + (size_t)b * Dd * HK + (size_t)o * HK + h * KK);
#pragma unroll
    for (int k = 0; k < KK / 2; k++)
        out[k] = __floats2half2_rn(acc[2 * k], acc[2 * k + 1]);
}

// -------- softmax over 16 keys per head, fusing split-K score reduce; P in fp16 --------
__global__ void __launch_bounds__(256) softmax_kernel(const float* __restrict__ scorep,
                                                      __half* __restrict__ P)
{
    const int tid = threadIdx.x;
    const size_t row = blockIdx.x * 16 + (tid >> 4);
    const int h = tid & 15;
    const size_t base = row * HK + h * KK;
    float s[KK];
#pragma unroll
    for (int q = 0; q < 4; q++) {
        float4 v = *(const float4*)(scorep + base + q * 4);
#pragma unroll
        for (int sp = 1; sp < SKS; sp++) {
            float4 t = *(const float4*)(scorep + (size_t)sp * BT * HK + base + q * 4);
            v.x += t.x; v.y += t.y; v.z += t.z; v.w += t.w;
        }
        s[q * 4 + 0] = v.x; s[q * 4 + 1] = v.y; s[q * 4 + 2] = v.z; s[q * 4 + 3] = v.w;
    }
    float m = s[0];
#pragma unroll
    for (int k = 1; k < KK; k++) m = fmaxf(m, s[k]);
    float sum = 0.f;
#pragma unroll
    for (int k = 0; k < KK; k++) { s[k] = expf(s[k] - m); sum += s[k]; }
    float rinv = 1.f / sum;
    __half2* po = (__half2*)(P + base);
#pragma unroll
    for (int k = 0; k < KK / 2; k++)
        po[k] = __floats2half2_rn(s[2 * k] * rinv, s[2 * k + 1] * rinv);
}

// ---------------- orchestration ----------------
extern "C" void kernel_launch(void* const* d_in, const int* in_sizes, int n_in,
                              void* d_out, int out_size)
{
    const float* x            = (const float*)d_in[0];
    const float* gist_theta   = (const float*)d_in[1];
    const float* gist_mag     = (const float*)d_in[2];
    const float* gist_weights = (const float*)d_in[3];
    const float* ln_sheaf_w   = (const float*)d_in[4];
    const float* ln_sheaf_b   = (const float*)d_in[5];
    const float* sheaf_thetas = (const float*)d_in[6];
    const float* alpha        = (const float*)d_in[7];
    const float* corr_W       = (const float*)d_in[8];
    const float* ln_gist_w    = (const float*)d_in[9];
    const float* ln_gist_b    = (const float*)d_in[10];
    const float* gist_strength= (const float*)d_in[11];
    const float* gr_ln_w      = (const float*)d_in[12];
    const float* gr_ln_b      = (const float*)d_in[13];
    const float* ln_gca_w     = (const float*)d_in[14];
    const float* ln_gca_b     = (const float*)d_in[15];
    const float* Wq           = (const float*)d_in[16];
    const float* Wk           = (const float*)d_in[17];
    const float* Wv           = (const float*)d_in[18];
    const float* Wo           = (const float*)d_in[19];
    const float* gist_up_W    = (const float*)d_in[20];
    const float* gist_up_b    = (const float*)d_in[21];
    float* out = (float*)d_out;

    float *repr, *Khb, *Vb, *packin, *Wpad, *part, *scorep, *shc, *shs, *gc, *gs;
    __half *S0h, *S1h, *Wh, *KWh, *VWTh, *Ph;
    cudaGetSymbolAddress((void**)&S0h, g_S0h);
    cudaGetSymbolAddress((void**)&S1h, g_S1h);
    cudaGetSymbolAddress((void**)&Wh, g_Wh);
    cudaGetSymbolAddress((void**)&repr, g_repr);
    cudaGetSymbolAddress((void**)&Khb, g_Kh);
    cudaGetSymbolAddress((void**)&Vb, g_Vv);
    cudaGetSymbolAddress((void**)&packin, g_packin);
    cudaGetSymbolAddress((void**)&Wpad, g_Wpad);
    cudaGetSymbolAddress((void**)&part, g_part);
    cudaGetSymbolAddress((void**)&KWh, g_KWh);
    cudaGetSymbolAddress((void**)&VWTh, g_VWTh);
    cudaGetSymbolAddress((void**)&scorep, g_scorep);
    cudaGetSymbolAddress((void**)&Ph, g_Ph);
    cudaGetSymbolAddress((void**)&shc, g_shc);
    cudaGetSymbolAddress((void**)&shs, g_shs);
    cudaGetSymbolAddress((void**)&gc, g_gc);
    cudaGetSymbolAddress((void**)&gs, g_gs);

    // one-time setup (outside capture: first call is the correctness run)
    static cudaStream_t s1 = nullptr;
    static cudaEvent_t evFork = nullptr, evKV = nullptr;
    if (!s1) {
        cudaStreamCreateWithFlags(&s1, cudaStreamNonBlocking);
        cudaEventCreateWithFlags(&evFork, cudaEventDisableTiming);
        cudaEventCreateWithFlags(&evKV, cudaEventDisableTiming);
        cudaFuncSetAttribute(gemm_mma, cudaFuncAttributeMaxDynamicSharedMemorySize,
                             GEMM_MMA_SMEM);
    }

    dim3 gemm_big(Dd / 128, BT / 128, 1);    // (16, 64)
    dim3 gemm_sc(HK / 128, BT / 128, SKS);   // (2, 64, 4)
    dim3 gemm_out(Dd / 128, BT / 128, 1);    // (16, 64)
    dim3 sk_grid(Dd / 128, NSPLIT);          // (16, 8)
    const int WN4 = Dd * Dd / 4;
    const int MN64 = 64 * Dd;

    cudaEventRecord(evFork, 0);

    // ---- s1: KV-prep chain (independent of the x path) ----
    cudaStreamWaitEvent(s1, evFork, 0);
    pack_gist_in<<<(64 * KPAD + 255) / 256, 256, 0, s1>>>(gist_theta, gist_mag, packin);
    pad_W_kernel<<<(Dd * KPAD + 255) / 256, 256, 0, s1>>>(gist_up_W, Wpad);
    splitk_nt<<<sk_grid, 256, 0, s1>>>(packin, Wpad, part, 64, Dd, KPAD, KPAD / NSPLIT);
    reduce_part<<<(MN64 + 255) / 256, 256, 0, s1>>>(part, repr, gist_up_b, MN64, Dd);
    splitk_nt<<<sk_grid, 256, 0, s1>>>(repr, Wk, part, 64, Dd, Dd, Dd / NSPLIT);
    reduce_part<<<(MN64 + 255) / 256, 256, 0, s1>>>(part, Khb, nullptr, MN64, Dd);
    splitk_nt<<<sk_grid, 256, 0, s1>>>(repr, Wv, part, 64, Dd, Dd, Dd / NSPLIT);
    reduce_part<<<(MN64 + 255) / 256, 256, 0, s1>>>(part, Vb, nullptr, MN64, Dd);
    kw_kernel<<<dim3(Bb * NH, Dd / 256), 256, 0, s1>>>(Khb, Wq, KWh);
    vwt_kernel<<<dim3(Bb * NH, Dd / 128), 128, 0, s1>>>(Vb, Wo, VWTh);
    cudaEventRecord(evKV, s1);

    // ---- main stream: stage 1 (sheaf) ----
    w_to_h<<<(WN4 + 255) / 256, 256>>>(corr_W, Wh, WN4);
    angles_kernel<<<(8 * DH + 255) / 256, 256>>>(sheaf_thetas, shc, shs,
                                                 gist_theta, gist_mag, gist_weights,
                                                 gist_strength, gc, gs);
    ln_kernel_h<<<BT, 256>>>(x, S0h, ln_sheaf_w, ln_sheaf_b);
    sheaf_pre_kernel<<<BT, 256>>>(S0h, S1h, shc, shs, alpha);
    // out = x + pre + pre @ corr_W^T   (fp16 MMA, fp32 accum)
    gemm_mma<<<gemm_big, 256, GEMM_MMA_SMEM>>>(S1h, Wh, out, x, S1h, Dd, Dd, Dd, 0, 0);

    // ---- stage 2: gist rotation (also emits S0h = fp16(LN_gca(out))) ----
    gist_fused_kernel<<<BT, 256>>>(out, S0h, ln_gist_w, ln_gist_b, gr_ln_w, gr_ln_b,
                                   ln_gca_w, ln_gca_b, gc, gs);

    // ---- join, then attention tail ----
    cudaStreamWaitEvent(0, evKV, 0);
    gemm_mma<<<gemm_sc, 256, GEMM_MMA_SMEM>>>(S0h, KWh, scorep, nullptr, nullptr,
                                              HK, Dd, Dd / SKS,
                                              (size_t)HK * Dd, (size_t)BT * HK);
    softmax_kernel<<<BT / 16, 256>>>(scorep, Ph);
    gemm_mma<<<gemm_out, 256, GEMM_MMA_SMEM>>>(Ph, VWTh, out, out, nullptr,
                                               Dd, HK, HK,
                                               (size_t)Dd * HK, 0);
}